// round 3
// baseline (speedup 1.0000x reference)
#include <cuda_runtime.h>
#include <math.h>

#define BATCH 300
#define ICH   256
#define HIN   38
#define WIN   38
#define OC1   128
#define H1    39
#define W1D   39
#define NPOS1 (H1*W1D)   /* 1521 */
#define KPOS  (38*38)    /* 1444 */

// scratch: conv1 output (relu'd), plus per-batch argmax results
__device__ float g_x[BATCH * OC1 * NPOS1];
__device__ int   g_bf[BATCH];
__device__ float g_bv[BATCH];

// ---------------------------------------------------------------------------
// K1: conv1 = relu(conv2d(base_feat, W1, pad=1)) -> g_x  (300,128,39,39)
// grid (39 rows, 300 batches), 256 threads.
// Each block: 1 output row (39 px, padded to 40), all 128 OC.
// Thread: 4 OC x 5 px accumulators.
// ---------------------------------------------------------------------------
__global__ __launch_bounds__(256) void conv1_kernel(
    const float* __restrict__ in, const float* __restrict__ w,
    const float* __restrict__ bias)
{
    __shared__ __align__(16) float sA[16 * 516];   // [icL] -> tap*128 + oc (row stride 516)
    __shared__ float sB[16 * 84];                  // [icL][r2*42 + col], col = input col + 1

    const int oh = blockIdx.x;
    const int b  = blockIdx.y;
    const int t  = threadIdx.x;
    const int oc0 = (t >> 3) * 4;   // 32 groups of 4 OC
    const int px0 = (t & 7) * 5;    // 8 groups of 5 px

    float acc0[5] = {0,0,0,0,0};
    float acc1[5] = {0,0,0,0,0};
    float acc2[5] = {0,0,0,0,0};
    float acc3[5] = {0,0,0,0,0};

    const float4* w4 = (const float4*)w;   // one float4 = one (oc,ic): taps 0..3

    for (int chunk = 0; chunk < 16; ++chunk) {
        const int ic0 = chunk * 16;
        __syncthreads();   // protect smem reuse from previous chunk's compute
        // ---- load weights: 16 ic x 4 tap x 128 oc ----
        #pragma unroll
        for (int i = 0; i < 8; ++i) {
            int e = t + i * 256;               // 0..2047 float4s
            int oc = e >> 4, icL = e & 15;
            float4 wv = w4[oc * 256 + ic0 + icL];
            int base = icL * 516 + oc;
            sA[base        ] = wv.x;
            sA[base + 128  ] = wv.y;
            sA[base + 256  ] = wv.z;
            sA[base + 384  ] = wv.w;
        }
        // ---- zero the pad columns (0, 39, 40, 41) ----
        if (t < 128) {
            int icL = t >> 3, r2 = (t >> 2) & 1, ci = t & 3;
            int col = (ci == 0) ? 0 : 38 + ci;
            sB[icL * 84 + r2 * 42 + col] = 0.f;
        }
        // ---- load input rows oh-1, oh (16 ic x 2 rows x 38 cols) ----
        #pragma unroll
        for (int i = 0; i < 5; ++i) {
            int e = t + i * 256;
            if (e < 1216) {
                int icL = e / 76, rr = e % 76;
                int r2 = rr / 38, c = rr % 38;
                int r = oh - 1 + r2;
                float v = (r >= 0 && r < HIN)
                        ? in[((b * ICH + ic0 + icL) * HIN + r) * WIN + c] : 0.f;
                sB[icL * 84 + r2 * 42 + c + 1] = v;
            }
        }
        __syncthreads();
        // ---- compute ----
        #pragma unroll
        for (int icL = 0; icL < 16; ++icL) {
            #pragma unroll
            for (int kh = 0; kh < 2; ++kh) {
                #pragma unroll
                for (int kw = 0; kw < 2; ++kw) {
                    float4 a = *(const float4*)&sA[icL * 516 + (kh * 2 + kw) * 128 + oc0];
                    const float* bp = &sB[icL * 84 + kh * 42 + px0 + kw];
                    #pragma unroll
                    for (int p = 0; p < 5; ++p) {
                        float bv = bp[p];
                        acc0[p] += a.x * bv;
                        acc1[p] += a.y * bv;
                        acc2[p] += a.z * bv;
                        acc3[p] += a.w * bv;
                    }
                }
            }
        }
    }
    float4 bi = *(const float4*)&bias[oc0];
    #pragma unroll
    for (int p = 0; p < 5; ++p) {
        int ow = px0 + p;
        if (ow < W1D) {
            int base = ((b * OC1 + oc0) * H1 + oh) * W1D + ow;
            float v;
            v = acc0[p] + bi.x; g_x[base            ] = v > 0.f ? v : 0.f;
            v = acc1[p] + bi.y; g_x[base + NPOS1    ] = v > 0.f ? v : 0.f;
            v = acc2[p] + bi.z; g_x[base + 2*NPOS1  ] = v > 0.f ? v : 0.f;
            v = acc3[p] + bi.w; g_x[base + 3*NPOS1  ] = v > 0.f ? v : 0.f;
        }
    }
}

// ---------------------------------------------------------------------------
// K2: difference conv (Wc[a+4]-Wc[a]) + global argmax over f = a*1444 + pos.
// sigmoid is monotone => argmax of diff == argmax of softmax score.
// 1 block per batch, 256 threads, each owning 6 positions x 4 anchors.
// ---------------------------------------------------------------------------
__global__ __launch_bounds__(256) void cls_argmax_kernel(
    const float* __restrict__ Wc, const float* __restrict__ bc)
{
    __shared__ __align__(16) float wds[128 * 16];   // [ic][tap*4 + a]
    __shared__ float xs[4 * NPOS1];                 // 4 ic chunk
    __shared__ float rv[256];
    __shared__ int   rf[256];

    const int b = blockIdx.x, t = threadIdx.x;

    // weight differences: wds[ic][tap][a] = Wc[a+4] - Wc[a]
    #pragma unroll
    for (int i = 0; i < 8; ++i) {
        int e = t + i * 256;                 // 0..2047
        int ic = e >> 4, tap = (e >> 2) & 3, a = e & 3;
        wds[ic * 16 + tap * 4 + a] =
            Wc[(a + 4) * 512 + ic * 4 + tap] - Wc[a * 512 + ic * 4 + tap];
    }

    int  offs[6];
    bool valid[6];
    #pragma unroll
    for (int i = 0; i < 6; ++i) {
        int p = t + i * 256;
        valid[i] = (p < KPOS);
        int pc = valid[i] ? p : 0;
        offs[i] = (pc / 38) * 39 + (pc % 38);   // pos -> x row offset
    }

    float acc[6][4];
    #pragma unroll
    for (int i = 0; i < 6; ++i)
        #pragma unroll
        for (int a = 0; a < 4; ++a) acc[i][a] = 0.f;

    const float* xb = g_x + (size_t)b * OC1 * NPOS1;

    for (int chunk = 0; chunk < 32; ++chunk) {
        __syncthreads();
        #pragma unroll
        for (int i = 0; i < 24; ++i) {
            int e = t + i * 256;
            if (e < 4 * NPOS1) xs[e] = xb[chunk * 4 * NPOS1 + e];
        }
        __syncthreads();
        #pragma unroll
        for (int icL = 0; icL < 4; ++icL) {
            int icg = chunk * 4 + icL;
            #pragma unroll
            for (int tap = 0; tap < 4; ++tap) {
                float4 wv = *(const float4*)&wds[icg * 16 + tap * 4];
                int bidx = icL * NPOS1 + (tap >> 1) * 39 + (tap & 1);
                #pragma unroll
                for (int i = 0; i < 6; ++i) {
                    float xv = xs[bidx + offs[i]];
                    acc[i][0] += wv.x * xv;
                    acc[i][1] += wv.y * xv;
                    acc[i][2] += wv.z * xv;
                    acc[i][3] += wv.w * xv;
                }
            }
        }
    }

    float bd[4];
    #pragma unroll
    for (int a = 0; a < 4; ++a) bd[a] = bc[a + 4] - bc[a];

    float bv = -1e30f; int bf = 0x7fffffff;
    #pragma unroll
    for (int i = 0; i < 6; ++i) {
        if (valid[i]) {
            int p = t + i * 256;
            #pragma unroll
            for (int a = 0; a < 4; ++a) {
                float v = acc[i][a] + bd[a];
                int f = a * KPOS + p;
                if (v > bv || (v == bv && f < bf)) { bv = v; bf = f; }
            }
        }
    }
    rv[t] = bv; rf[t] = bf;
    __syncthreads();
    for (int s = 128; s > 0; s >>= 1) {
        if (t < s) {
            float v2 = rv[t + s]; int f2 = rf[t + s];
            if (v2 > rv[t] || (v2 == rv[t] && f2 < rf[t])) { rv[t] = v2; rf[t] = f2; }
        }
        __syncthreads();
    }
    if (t == 0) { g_bf[b] = rf[0]; g_bv[b] = rv[0]; }
}

// ---------------------------------------------------------------------------
// K3: deltas conv at the single selected position (4 channels), box assembly.
// f interpreted in proposal space: pos = f>>2, anchor = f&3.
// 1 block per batch, 128 threads (one per ic).
// ---------------------------------------------------------------------------
__global__ __launch_bounds__(128) void box_kernel(
    const float* __restrict__ Wb, const float* __restrict__ bb,
    const float* __restrict__ anchors, const float* __restrict__ im_info,
    float* __restrict__ out)
{
    __shared__ float red[4][128];
    const int b = blockIdx.x, ic = threadIdx.x;
    const int f  = g_bf[b];
    const int kp = f >> 2, ap = f & 3;
    const int hp = kp / 38, wp = kp % 38;

    const float* xb = g_x + ((size_t)b * OC1 + ic) * NPOS1 + hp * 39 + wp;
    float x0 = xb[0], x1 = xb[1], x2 = xb[39], x3 = xb[40];

    #pragma unroll
    for (int j = 0; j < 4; ++j) {
        const float* wq = Wb + (ap * 4 + j) * 512 + ic * 4;
        red[j][ic] = x0 * wq[0] + x1 * wq[1] + x2 * wq[2] + x3 * wq[3];
    }
    __syncthreads();
    if (ic < 4) {
        float s = 0.f;
        #pragma unroll 8
        for (int k = 0; k < 128; ++k) s += red[ic][k];
        s += bb[ap * 4 + ic];
        float shift = (ic & 1) ? hp * 16.f : wp * 16.f;
        float sc = im_info[0];
        float box = (anchors[ap * 4 + ic] + shift + s) * sc;
        out[b * 9 + ic]     = truncf(box / sc);
        out[b * 9 + 4 + ic] = box;
    }
    if (ic == 4) out[b * 9 + 8] = 1.f / (1.f + expf(-g_bv[b]));
}

// ---------------------------------------------------------------------------
// K4: proposal loss (single thread). Replicates reference exactly, including
// the "maximum" used for xi2/yi2.
// ---------------------------------------------------------------------------
__global__ void loss_kernel(const float* __restrict__ gt,
                            const int* __restrict__ central,
                            float* __restrict__ out, int out_size)
{
    int idx = central[0];            // FRAMES_PER_VIDEO * 0 + central_pos
    bool valid = idx < BATCH;
    int ix = idx < 0 ? 0 : (idx > BATCH - 1 ? BATCH - 1 : idx);
    float vb0 = out[ix * 9 + 4], vb1 = out[ix * 9 + 5];
    float vb2 = out[ix * 9 + 6], vb3 = out[ix * 9 + 7];
    float vs  = out[ix * 9 + 8];
    float xi1 = fmaxf(gt[0], vb0);
    float yi1 = fmaxf(gt[1], vb1);
    float xi2 = fmaxf(gt[2], vb2);
    float yi2 = fmaxf(gt[3], vb3);
    float inter = (xi2 - xi1) * (yi2 - yi1);
    float a1 = (gt[2] - gt[0]) * (gt[3] - gt[1]);
    float a2 = (vb2 - vb0) * (vb3 - vb1);
    float iou = inter / (a1 + a2 - inter);
    float lv = (iou > 0.7f) ? -logf(vs + 1e-5f) : -logf(1.f - vs + 1e-5f);
    out[out_size - 1] = valid ? lv : 0.f;
}

// ---------------------------------------------------------------------------
extern "C" void kernel_launch(void* const* d_in, const int* in_sizes, int n_in,
                              void* d_out, int out_size)
{
    const float* base_feat = (const float*)d_in[0];
    const int*   central   = (const int*)  d_in[1];
    const float* im_info   = (const float*)d_in[2];
    const float* gt_boxes  = (const float*)d_in[3];
    const float* W1        = (const float*)d_in[4];
    const float* b1        = (const float*)d_in[5];
    const float* Wc        = (const float*)d_in[6];
    const float* bc        = (const float*)d_in[7];
    const float* Wb        = (const float*)d_in[8];
    const float* bb        = (const float*)d_in[9];
    const float* anchors   = (const float*)d_in[10];
    float* out = (float*)d_out;

    conv1_kernel<<<dim3(H1, BATCH), 256>>>(base_feat, W1, b1);
    cls_argmax_kernel<<<BATCH, 256>>>(Wc, bc);
    box_kernel<<<BATCH, 128>>>(Wb, bb, anchors, im_info, out);
    loss_kernel<<<1, 1>>>(gt_boxes, central, out, out_size);
}

// round 5
// speedup vs baseline: 1.8715x; 1.8715x over previous
#include <cuda_runtime.h>
#include <cuda_bf16.h>
#include <math.h>
#include <cstdint>

#define BATCH 300
#define ICH   256
#define OC1   128
#define NPOS1 1521
#define KPOS  1444

// ------------------- device scratch -------------------
__device__ float g_x[BATCH * OC1 * NPOS1];     // conv1 output, [b][oc][oh*39+ow]
__device__ int   g_bf[BATCH];
__device__ float g_bv[BATCH];
// bf16 split weight images: [chunk c][oc][k] (128B rows), c = k-chunk of 64
__device__ __align__(16) unsigned char g_Ah[16 * 16384];
__device__ __align__(16) unsigned char g_Al[16 * 16384];

__device__ __forceinline__ uint32_t smem_u32(const void* p) {
    return (uint32_t)__cvta_generic_to_shared(p);
}
__device__ __forceinline__ void ldmx4(uint32_t* r, uint32_t addr) {
    asm volatile("ldmatrix.sync.aligned.m8n8.x4.shared.b16 {%0,%1,%2,%3}, [%4];"
        : "=r"(r[0]), "=r"(r[1]), "=r"(r[2]), "=r"(r[3]) : "r"(addr));
}
__device__ __forceinline__ void mma16816(float* d, const uint32_t* a, const uint32_t* b) {
    asm volatile("mma.sync.aligned.m16n8k16.row.col.f32.bf16.bf16.f32 "
        "{%0,%1,%2,%3},{%4,%5,%6,%7},{%8,%9},{%0,%1,%2,%3};"
        : "+f"(d[0]), "+f"(d[1]), "+f"(d[2]), "+f"(d[3])
        : "r"(a[0]), "r"(a[1]), "r"(a[2]), "r"(a[3]), "r"(b[0]), "r"(b[1]));
}
__device__ __forceinline__ void cpasync4(uint32_t dst, const void* src, uint32_t sz) {
    asm volatile("cp.async.ca.shared.global [%0], [%1], 4, %2;"
        :: "r"(dst), "l"(src), "r"(sz));
}
__device__ __forceinline__ void cpasync16(uint32_t dst, const void* src) {
    asm volatile("cp.async.cg.shared.global [%0], [%1], 16;" :: "r"(dst), "l"(src));
}

// ---------------------------------------------------------------------------
// K0: split W1 (fp32) into bf16 hi/lo images, [c][oc][k] with 128B rows.
// k = icL*4 + tap is contiguous in W1's [ic][kh][kw] order.
// ---------------------------------------------------------------------------
__global__ __launch_bounds__(256) void prep_w_kernel(const float* __restrict__ W1) {
    int p = blockIdx.x * 256 + threadIdx.x;   // 65536 bf16-pairs
    int oc = p >> 9;
    int kk = (p & 511) << 1;                  // even k in [0,1024)
    int c = kk >> 6, k = kk & 63;
    float v0 = W1[oc * 1024 + c * 64 + k];
    float v1 = W1[oc * 1024 + c * 64 + k + 1];
    __nv_bfloat16 h0 = __float2bfloat16(v0), h1 = __float2bfloat16(v1);
    __nv_bfloat16 l0 = __float2bfloat16(v0 - __bfloat162float(h0));
    __nv_bfloat16 l1 = __float2bfloat16(v1 - __bfloat162float(h1));
    uint32_t uh = ((uint32_t)__bfloat16_as_ushort(h1) << 16) | __bfloat16_as_ushort(h0);
    uint32_t ul = ((uint32_t)__bfloat16_as_ushort(l1) << 16) | __bfloat16_as_ushort(l0);
    uint32_t off = (uint32_t)(c * 16384 + oc * 128 + k * 2);
    *(uint32_t*)(g_Ah + off) = uh;
    *(uint32_t*)(g_Al + off) = ul;
}

// ---------------------------------------------------------------------------
// K1: conv1 via ldmatrix + mma.sync (bf16 3-pass split, fp32 accum).
// CTA: 128 oc x 128 positions on the 40-stride padded grid. 13 tiles/batch.
// 8 warps: 4(M) x 2(N); warp tile 32 x 64.
// SMEM tiles stored [row][k] bf16, row stride 144B (ldmatrix conflict-free).
// ---------------------------------------------------------------------------
#define SAB     144                   /* row stride bytes (64 bf16 + 8 pad) */
#define OFF_AL  18432
#define OFF_BH  36864
#define OFF_BL  55296
#define BUFSZ   73728
#define STAGE_OFF 147456
#define STAGE_SZ  11264               /* 16 icL x 176 fp32 */
#define SMEM_TC   169984

__global__ __launch_bounds__(256, 1) void conv1_tc_kernel(
    const float* __restrict__ in, const float* __restrict__ bias)
{
    extern __shared__ __align__(16) unsigned char sm[];
    const uint32_t smb = smem_u32(sm);
    const int t = threadIdx.x;
    const int b = blockIdx.x / 13;
    const int tile = blockIdx.x - b * 13;
    const int nbase = tile * 128;
    const float* inb = in + (size_t)b * (ICH * KPOS);

    const int wid = t >> 5, l = t & 31;
    const int wm = wid & 3, wn = wid >> 2;
    // ldmatrix lane address offsets (within tile region)
    const uint32_t aoff = (uint32_t)((wm * 32 + (l & 15)) * SAB + (l >> 4) * 16);
    const uint32_t boff = (uint32_t)((wn * 64 + (l & 7) + ((l >> 4) & 1) * 8) * SAB
                                     + ((l >> 3) & 1) * 16);
    // B-build mapping
    const int bn = t & 127, bkq = t >> 7;

    float acc[2][8][4];
    #pragma unroll
    for (int mt = 0; mt < 2; ++mt)
        #pragma unroll
        for (int nf = 0; nf < 8; ++nf)
            #pragma unroll
            for (int r = 0; r < 4; ++r) acc[mt][nf][r] = 0.f;

    // ---- issue phase: async loads for chunk c ----
    auto issue = [&](int c) {
        const int buf = c & 1;
        // input staging (fp32, zfill for padding)
        uint32_t sdst = smb + STAGE_OFF + buf * STAGE_SZ;
        #pragma unroll
        for (int i = 0; i < 11; ++i) {
            int e = t + i * 256;                  // 0..2815 = icL*176 + s
            int icL = e / 176, s = e - icL * 176;
            int m = nbase - 40 + s;
            const float* src = inb; uint32_t sz = 0;
            if (m >= 0) {
                int iy = m / 40, x = m - iy * 40 - 1;
                if (iy < 38 && x >= 0 && x < 38) {
                    src = &inb[((c * 16 + icL) * 38 + iy) * 38 + x];
                    sz = 4;
                }
            }
            cpasync4(sdst + e * 4, src, sz);
        }
        // A images (raw bf16 copy into 144B-stride rows)
        uint32_t abase = smb + buf * BUFSZ;
        #pragma unroll
        for (int i = 0; i < 8; ++i) {
            int e = t + i * 256;                  // 0..2047 16B-chunks
            int p = e >> 10, oc = (e >> 3) & 127, seg = e & 7;
            const unsigned char* src = (p ? g_Al : g_Ah) + c * 16384 + oc * 128 + seg * 16;
            cpasync16(abase + p * OFF_AL + oc * SAB + seg * 16, src);
        }
        asm volatile("cp.async.commit_group;" ::: "memory");
    };

    // ---- build phase: im2col B (split bf16) from fp32 staging ----
    auto build = [&](int c) {
        const int buf = c & 1;
        const float* stg = (const float*)(sm + STAGE_OFF + buf * STAGE_SZ);
        unsigned char* bp = sm + buf * BUFSZ;
        #pragma unroll
        for (int j = 0; j < 32; j += 2) {
            int k = bkq * 32 + j;                 // even
            int icL = k >> 2, kh = (k >> 1) & 1;
            int s0 = bn + kh * 40 + (k & 1);      // k even -> kw=0
            float v0 = stg[icL * 176 + s0];
            float v1 = stg[icL * 176 + s0 + 1];
            __nv_bfloat16 h0 = __float2bfloat16(v0), h1 = __float2bfloat16(v1);
            __nv_bfloat16 l0 = __float2bfloat16(v0 - __bfloat162float(h0));
            __nv_bfloat16 l1 = __float2bfloat16(v1 - __bfloat162float(h1));
            uint32_t uh = ((uint32_t)__bfloat16_as_ushort(h1) << 16) | __bfloat16_as_ushort(h0);
            uint32_t ul = ((uint32_t)__bfloat16_as_ushort(l1) << 16) | __bfloat16_as_ushort(l0);
            uint32_t off = (uint32_t)(bn * SAB + k * 2);
            *(uint32_t*)(bp + OFF_BH + off) = uh;
            *(uint32_t*)(bp + OFF_BL + off) = ul;
        }
    };

    // ---- compute phase: 4 k16 steps, 3 split passes ----
    auto compute = [&](int c) {
        uint32_t base = smb + (c & 1) * BUFSZ;
        #pragma unroll
        for (int ks = 0; ks < 4; ++ks) {
            uint32_t koff = ks * 32;
            uint32_t Ah[2][4], Al[2][4], Bh[8][2], Bl[8][2];
            ldmx4(Ah[0], base + aoff + koff);
            ldmx4(Ah[1], base + aoff + 16 * SAB + koff);
            ldmx4(Al[0], base + OFF_AL + aoff + koff);
            ldmx4(Al[1], base + OFF_AL + aoff + 16 * SAB + koff);
            #pragma unroll
            for (int q = 0; q < 4; ++q) {
                uint32_t r[4];
                ldmx4(r, base + OFF_BH + boff + q * (16 * SAB) + koff);
                Bh[2*q][0] = r[0]; Bh[2*q][1] = r[1];
                Bh[2*q+1][0] = r[2]; Bh[2*q+1][1] = r[3];
                ldmx4(r, base + OFF_BL + boff + q * (16 * SAB) + koff);
                Bl[2*q][0] = r[0]; Bl[2*q][1] = r[1];
                Bl[2*q+1][0] = r[2]; Bl[2*q+1][1] = r[3];
            }
            #pragma unroll
            for (int mt = 0; mt < 2; ++mt)
                #pragma unroll
                for (int nf = 0; nf < 8; ++nf) {
                    mma16816(acc[mt][nf], Ah[mt], Bh[nf]);
                    mma16816(acc[mt][nf], Ah[mt], Bl[nf]);
                    mma16816(acc[mt][nf], Al[mt], Bh[nf]);
                }
        }
    };

    // ---- pipeline ----
    issue(0);
    asm volatile("cp.async.wait_group 0;" ::: "memory");
    __syncthreads();
    build(0);
    __syncthreads();
    for (int c = 0; c < 16; ++c) {
        if (c < 15) issue(c + 1);
        compute(c);
        if (c < 15) {
            asm volatile("cp.async.wait_group 0;" ::: "memory");
            __syncthreads();
            build(c + 1);
            __syncthreads();
        }
    }

    // ---- epilogue: bias + relu, scattered stores into g_x ----
    float bia[2][2];
    #pragma unroll
    for (int mt = 0; mt < 2; ++mt) {
        int mb = wm * 32 + mt * 16 + (l >> 2);
        bia[mt][0] = __ldg(bias + mb);
        bia[mt][1] = __ldg(bias + mb + 8);
    }
    #pragma unroll
    for (int mt = 0; mt < 2; ++mt)
        #pragma unroll
        for (int nf = 0; nf < 8; ++nf)
            #pragma unroll
            for (int r = 0; r < 4; ++r) {
                int m = wm * 32 + mt * 16 + (l >> 2) + ((r >> 1) ? 8 : 0);
                int n = wn * 64 + nf * 8 + 2 * (l & 3) + (r & 1);
                int ng = nbase + n;
                int oh = ng / 40, ow = ng - oh * 40;
                if (oh < 39 && ow < 39) {
                    float v = acc[mt][nf][r] + bia[mt][r >> 1];
                    v = v > 0.f ? v : 0.f;
                    g_x[((size_t)(b * OC1 + m) * 39 + oh) * 39 + ow] = v;
                }
            }
}

// ---------------------------------------------------------------------------
// K2: difference conv (Wc[a+4]-Wc[a]) + global argmax over f = a*1444 + pos.
// ---------------------------------------------------------------------------
__global__ __launch_bounds__(256) void cls_argmax_kernel(
    const float* __restrict__ Wc, const float* __restrict__ bc)
{
    __shared__ __align__(16) float wds[128 * 16];
    __shared__ float xs[4 * NPOS1];
    __shared__ float rv[256];
    __shared__ int   rf[256];

    const int b = blockIdx.x, t = threadIdx.x;

    #pragma unroll
    for (int i = 0; i < 8; ++i) {
        int e = t + i * 256;
        int ic = e >> 4, tap = (e >> 2) & 3, a = e & 3;
        wds[ic * 16 + tap * 4 + a] =
            Wc[(a + 4) * 512 + ic * 4 + tap] - Wc[a * 512 + ic * 4 + tap];
    }

    int  offs[6];
    bool valid[6];
    #pragma unroll
    for (int i = 0; i < 6; ++i) {
        int p = t + i * 256;
        valid[i] = (p < KPOS);
        int pc = valid[i] ? p : 0;
        offs[i] = (pc / 38) * 39 + (pc % 38);
    }

    float acc[6][4];
    #pragma unroll
    for (int i = 0; i < 6; ++i)
        #pragma unroll
        for (int a = 0; a < 4; ++a) acc[i][a] = 0.f;

    const float* xb = g_x + (size_t)b * OC1 * NPOS1;

    for (int chunk = 0; chunk < 32; ++chunk) {
        __syncthreads();
        #pragma unroll
        for (int i = 0; i < 24; ++i) {
            int e = t + i * 256;
            if (e < 4 * NPOS1) xs[e] = xb[chunk * 4 * NPOS1 + e];
        }
        __syncthreads();
        #pragma unroll
        for (int icL = 0; icL < 4; ++icL) {
            int icg = chunk * 4 + icL;
            #pragma unroll
            for (int tap = 0; tap < 4; ++tap) {
                float4 wv = *(const float4*)&wds[icg * 16 + tap * 4];
                int bidx = icL * NPOS1 + (tap >> 1) * 39 + (tap & 1);
                #pragma unroll
                for (int i = 0; i < 6; ++i) {
                    float xv = xs[bidx + offs[i]];
                    acc[i][0] += wv.x * xv;
                    acc[i][1] += wv.y * xv;
                    acc[i][2] += wv.z * xv;
                    acc[i][3] += wv.w * xv;
                }
            }
        }
    }

    float bd[4];
    #pragma unroll
    for (int a = 0; a < 4; ++a) bd[a] = bc[a + 4] - bc[a];

    float bv = -1e30f; int bf = 0x7fffffff;
    #pragma unroll
    for (int i = 0; i < 6; ++i) {
        if (valid[i]) {
            int p = t + i * 256;
            #pragma unroll
            for (int a = 0; a < 4; ++a) {
                float v = acc[i][a] + bd[a];
                int f = a * KPOS + p;
                if (v > bv || (v == bv && f < bf)) { bv = v; bf = f; }
            }
        }
    }
    rv[t] = bv; rf[t] = bf;
    __syncthreads();
    for (int s = 128; s > 0; s >>= 1) {
        if (t < s) {
            float v2 = rv[t + s]; int f2 = rf[t + s];
            if (v2 > rv[t] || (v2 == rv[t] && f2 < rf[t])) { rv[t] = v2; rf[t] = f2; }
        }
        __syncthreads();
    }
    if (t == 0) { g_bf[b] = rf[0]; g_bv[b] = rv[0]; }
}

// ---------------------------------------------------------------------------
// K3: deltas conv only at the selected position, box assembly.
// ---------------------------------------------------------------------------
__global__ __launch_bounds__(128) void box_kernel(
    const float* __restrict__ Wb, const float* __restrict__ bb,
    const float* __restrict__ anchors, const float* __restrict__ im_info,
    float* __restrict__ out)
{
    __shared__ float red[4][128];
    const int b = blockIdx.x, ic = threadIdx.x;
    const int f  = g_bf[b];
    const int kp = f >> 2, ap = f & 3;
    const int hp = kp / 38, wp = kp % 38;

    const float* xb = g_x + ((size_t)b * OC1 + ic) * NPOS1 + hp * 39 + wp;
    float x0 = xb[0], x1 = xb[1], x2 = xb[39], x3 = xb[40];

    #pragma unroll
    for (int j = 0; j < 4; ++j) {
        const float* wq = Wb + (ap * 4 + j) * 512 + ic * 4;
        red[j][ic] = x0 * wq[0] + x1 * wq[1] + x2 * wq[2] + x3 * wq[3];
    }
    __syncthreads();
    if (ic < 4) {
        float s = 0.f;
        #pragma unroll 8
        for (int k = 0; k < 128; ++k) s += red[ic][k];
        s += bb[ap * 4 + ic];
        float shift = (ic & 1) ? hp * 16.f : wp * 16.f;
        float sc = im_info[0];
        float box = (anchors[ap * 4 + ic] + shift + s) * sc;
        out[b * 9 + ic]     = truncf(box / sc);
        out[b * 9 + 4 + ic] = box;
    }
    if (ic == 4) out[b * 9 + 8] = 1.f / (1.f + expf(-g_bv[b]));
}

// ---------------------------------------------------------------------------
// K4: proposal loss.
// ---------------------------------------------------------------------------
__global__ void loss_kernel(const float* __restrict__ gt,
                            const int* __restrict__ central,
                            float* __restrict__ out, int out_size)
{
    int idx = central[0];
    bool valid = idx < BATCH;
    int ix = idx < 0 ? 0 : (idx > BATCH - 1 ? BATCH - 1 : idx);
    float vb0 = out[ix * 9 + 4], vb1 = out[ix * 9 + 5];
    float vb2 = out[ix * 9 + 6], vb3 = out[ix * 9 + 7];
    float vs  = out[ix * 9 + 8];
    float xi1 = fmaxf(gt[0], vb0);
    float yi1 = fmaxf(gt[1], vb1);
    float xi2 = fmaxf(gt[2], vb2);
    float yi2 = fmaxf(gt[3], vb3);
    float inter = (xi2 - xi1) * (yi2 - yi1);
    float a1 = (gt[2] - gt[0]) * (gt[3] - gt[1]);
    float a2 = (vb2 - vb0) * (vb3 - vb1);
    float iou = inter / (a1 + a2 - inter);
    float lv = (iou > 0.7f) ? -logf(vs + 1e-5f) : -logf(1.f - vs + 1e-5f);
    out[out_size - 1] = valid ? lv : 0.f;
}

// ---------------------------------------------------------------------------
extern "C" void kernel_launch(void* const* d_in, const int* in_sizes, int n_in,
                              void* d_out, int out_size)
{
    const float* base_feat = (const float*)d_in[0];
    const int*   central   = (const int*)  d_in[1];
    const float* im_info   = (const float*)d_in[2];
    const float* gt_boxes  = (const float*)d_in[3];
    const float* W1        = (const float*)d_in[4];
    const float* b1        = (const float*)d_in[5];
    const float* Wc        = (const float*)d_in[6];
    const float* bc        = (const float*)d_in[7];
    const float* Wb        = (const float*)d_in[8];
    const float* bb        = (const float*)d_in[9];
    const float* anchors   = (const float*)d_in[10];
    float* out = (float*)d_out;

    cudaFuncSetAttribute(conv1_tc_kernel,
                         cudaFuncAttributeMaxDynamicSharedMemorySize, SMEM_TC);

    prep_w_kernel<<<256, 256>>>(W1);
    conv1_tc_kernel<<<BATCH * 13, 256, SMEM_TC>>>(base_feat, b1);
    cls_argmax_kernel<<<BATCH, 256>>>(Wc, bc);
    box_kernel<<<BATCH, 128>>>(Wb, bb, anchors, im_info, out);
    loss_kernel<<<1, 1>>>(gt_boxes, central, out, out_size);
}

// round 6
// speedup vs baseline: 2.2614x; 1.2084x over previous
#include <cuda_runtime.h>
#include <cuda_bf16.h>
#include <math.h>
#include <cstdint>

#define BATCH 300
#define ICH   256
#define OC1   128
#define NPOS1 1521
#define KPOS  1444

// ------------------- device scratch -------------------
__device__ float g_x[BATCH * OC1 * NPOS1];     // conv1 output, [b][oc][oh*39+ow]
__device__ int   g_bf[BATCH];
__device__ float g_bv[BATCH];
// weight images, k-order (tap,icL): [c][oc][64k] bf16, 128B rows
__device__ __align__(16) unsigned char g_Ah[16 * 16384];
__device__ __align__(16) unsigned char g_Al[16 * 16384];
// position-major split input: [b][kpos][ic] bf16
__device__ __nv_bfloat16 g_pH[(size_t)BATCH * KPOS * ICH];
__device__ __nv_bfloat16 g_pL[(size_t)BATCH * KPOS * ICH];

__device__ __forceinline__ uint32_t smem_u32(const void* p) {
    return (uint32_t)__cvta_generic_to_shared(p);
}
__device__ __forceinline__ void ldmx4(uint32_t* r, uint32_t addr) {
    asm volatile("ldmatrix.sync.aligned.m8n8.x4.shared.b16 {%0,%1,%2,%3}, [%4];"
        : "=r"(r[0]), "=r"(r[1]), "=r"(r[2]), "=r"(r[3]) : "r"(addr));
}
__device__ __forceinline__ void mma16816(float* d, const uint32_t* a, const uint32_t* b) {
    asm volatile("mma.sync.aligned.m16n8k16.row.col.f32.bf16.bf16.f32 "
        "{%0,%1,%2,%3},{%4,%5,%6,%7},{%8,%9},{%0,%1,%2,%3};"
        : "+f"(d[0]), "+f"(d[1]), "+f"(d[2]), "+f"(d[3])
        : "r"(a[0]), "r"(a[1]), "r"(a[2]), "r"(a[3]), "r"(b[0]), "r"(b[1]));
}
__device__ __forceinline__ void cpasync16z(uint32_t dst, const void* src, uint32_t sz) {
    asm volatile("cp.async.cg.shared.global [%0], [%1], 16, %2;"
        :: "r"(dst), "l"(src), "r"(sz));
}
__device__ __forceinline__ void split_bf16(float v, __nv_bfloat16& h, __nv_bfloat16& l) {
    h = __float2bfloat16(v);
    l = __float2bfloat16(v - __bfloat162float(h));
}

// ---------------------------------------------------------------------------
// K0a: split W1 into bf16 hi/lo images [c][oc][64k], k = tap*16 + icL.
// ---------------------------------------------------------------------------
__global__ __launch_bounds__(256) void prep_w_kernel(const float* __restrict__ W1) {
    int p = blockIdx.x * 256 + threadIdx.x;   // 65536 bf16-pairs
    int oc = p >> 9;
    int kk = (p & 511) << 1;                  // even k in [0,1024)
    int c = kk >> 6, k2 = kk & 63;
    int tap = k2 >> 4, icL = k2 & 15;         // k2 even -> icL even, same tap for k2+1
    float v0 = W1[oc * 1024 + (c * 16 + icL) * 4 + tap];
    float v1 = W1[oc * 1024 + (c * 16 + icL + 1) * 4 + tap];
    __nv_bfloat16 h0, l0, h1, l1;
    split_bf16(v0, h0, l0);
    split_bf16(v1, h1, l1);
    uint32_t uh = ((uint32_t)__bfloat16_as_ushort(h1) << 16) | __bfloat16_as_ushort(h0);
    uint32_t ul = ((uint32_t)__bfloat16_as_ushort(l1) << 16) | __bfloat16_as_ushort(l0);
    uint32_t off = (uint32_t)(c * 16384 + oc * 128 + k2 * 2);
    *(uint32_t*)(g_Ah + off) = uh;
    *(uint32_t*)(g_Al + off) = ul;
}

// ---------------------------------------------------------------------------
// K0b: transpose+split input: [b][ic][1444] fp32 -> [b][pos][ic] bf16 hi/lo.
// grid (19 pos-tiles of 76, 8 ic-blocks of 32, 300 b), 256 threads.
// ---------------------------------------------------------------------------
__global__ __launch_bounds__(256) void prep_in_kernel(const float* __restrict__ in) {
    __shared__ float st[32][77];
    const int pt = blockIdx.x, icb = blockIdx.y, b = blockIdx.z;
    const int t = threadIdx.x;
    const float* src = in + ((size_t)(b * ICH + icb * 32) * KPOS) + pt * 76;
    #pragma unroll
    for (int i = 0; i < 10; ++i) {
        int e = t + i * 256;
        if (e < 2432) {
            int icL = e / 76, s = e - icL * 76;
            st[icL][s] = src[(size_t)icL * KPOS + s];
        }
    }
    __syncthreads();
    #pragma unroll
    for (int i = 0; i < 10; ++i) {
        int e = t + i * 256;
        if (e < 2432) {
            int posL = e >> 5, icL = e & 31;
            float v = st[icL][posL];
            __nv_bfloat16 h, l;
            split_bf16(v, h, l);
            size_t d = (size_t)(b * KPOS + pt * 76 + posL) * ICH + icb * 32 + icL;
            g_pH[d] = h;
            g_pL[d] = l;
        }
    }
}

// ---------------------------------------------------------------------------
// K1: conv1 via tap-decomposed GEMMs, ldmatrix + mma.sync bf16 3-pass split.
// CTA: 128 oc x 128 positions (40-grid), 13 tiles/batch. 8 warps 4(M)x2(N).
// Chunk = 16 ic; k-steps = 4 taps x k16. B tile = input rows [pos][16 ic].
// ---------------------------------------------------------------------------
#define APITCH 144
#define BPITCH 48
#define OFF_AL 18432
#define OFF_BH 36864
#define OFF_BL 45312
#define BUFSZ  53760
#define SMEM_TC (2 * BUFSZ)

__global__ __launch_bounds__(256, 1) void conv1_tc_kernel(
    const float* __restrict__ bias)
{
    extern __shared__ __align__(16) unsigned char sm[];
    const uint32_t smb = smem_u32(sm);
    const int t = threadIdx.x;
    const int b = blockIdx.x / 13;
    const int tile = blockIdx.x - b * 13;
    const int nbase = tile * 128;

    const int wid = t >> 5, l = t & 31;
    const int wm = wid & 3, wn = wid >> 2;
    const uint32_t aoff = (uint32_t)((wm * 32 + (l & 15)) * APITCH + ((l >> 4) & 1) * 16);
    const uint32_t boff = (uint32_t)((wn * 64 + (l & 7) + ((l >> 4) & 1) * 8) * BPITCH
                                     + ((l >> 3) & 1) * 16);

    float acc[2][8][4];
    #pragma unroll
    for (int mt = 0; mt < 2; ++mt)
        #pragma unroll
        for (int nf = 0; nf < 8; ++nf)
            #pragma unroll
            for (int r = 0; r < 4; ++r) acc[mt][nf][r] = 0.f;

    // ---- issue: async loads for chunk c into buffer c&1 ----
    auto issue = [&](int c) {
        const uint32_t bb = smb + (c & 1) * BUFSZ;
        // A: 2 planes x 128 oc x 8 segs of 16B
        #pragma unroll
        for (int i = 0; i < 8; ++i) {
            int e = t + i * 256;                 // 0..2047
            int pl = e >> 10, r = e & 1023;      // r = oc*8+seg
            const unsigned char* src = (pl ? g_Al : g_Ah) + c * 16384 + r * 16;
            cpasync16z(bb + pl * OFF_AL + (r >> 3) * APITCH + (r & 7) * 16, src, 16);
        }
        // B: 2 planes x 176 rows x 2 halves of 16B (row = 16 ic of one position)
        #pragma unroll
        for (int i = 0; i < 3; ++i) {
            int e = t + i * 256;
            if (e < 704) {
                int pl = e >= 352 ? 1 : 0;
                int r = e - pl * 352;
                int s = r >> 1, half = r & 1;
                int m = nbase - 40 + s;
                int iy = m / 40;
                int px = m - iy * 40;
                bool valid = (m >= 0) && (iy < 38) && (px >= 1) && (px <= 38);
                size_t si = valid ? ((size_t)(b * KPOS + iy * 38 + px - 1) * ICH
                                     + c * 16 + half * 8) : 0;
                const __nv_bfloat16* src = (pl ? g_pL : g_pH) + si;
                cpasync16z(bb + OFF_BH + pl * (OFF_BL - OFF_BH) + s * BPITCH + half * 16,
                           src, valid ? 16u : 0u);
            }
        }
        asm volatile("cp.async.commit_group;" ::: "memory");
    };

    // ---- compute chunk c: 4 taps, each k16, 3 split passes ----
    auto compute = [&](int c) {
        const uint32_t bb = smb + (c & 1) * BUFSZ;
        #pragma unroll
        for (int tap = 0; tap < 4; ++tap) {
            const uint32_t koff = tap * 32;
            const int dlt = (tap >> 1) * 40 + (tap & 1);
            uint32_t Ah[2][4], Al[2][4], Bh[8][2], Bl[8][2];
            ldmx4(Ah[0], bb + aoff + koff);
            ldmx4(Ah[1], bb + aoff + 16 * APITCH + koff);
            ldmx4(Al[0], bb + OFF_AL + aoff + koff);
            ldmx4(Al[1], bb + OFF_AL + aoff + 16 * APITCH + koff);
            #pragma unroll
            for (int g = 0; g < 4; ++g) {
                uint32_t r[4];
                ldmx4(r, bb + OFF_BH + boff + (dlt + g * 16) * BPITCH);
                Bh[2*g][0] = r[0]; Bh[2*g][1] = r[1];
                Bh[2*g+1][0] = r[2]; Bh[2*g+1][1] = r[3];
                ldmx4(r, bb + OFF_BL + boff + (dlt + g * 16) * BPITCH);
                Bl[2*g][0] = r[0]; Bl[2*g][1] = r[1];
                Bl[2*g+1][0] = r[2]; Bl[2*g+1][1] = r[3];
            }
            #pragma unroll
            for (int mt = 0; mt < 2; ++mt)
                #pragma unroll
                for (int nf = 0; nf < 8; ++nf) {
                    mma16816(acc[mt][nf], Ah[mt], Bh[nf]);
                    mma16816(acc[mt][nf], Ah[mt], Bl[nf]);
                    mma16816(acc[mt][nf], Al[mt], Bh[nf]);
                }
        }
    };

    // ---- pipeline ----
    issue(0);
    for (int c = 0; c < 16; ++c) {
        if (c < 15) {
            issue(c + 1);
            asm volatile("cp.async.wait_group 1;" ::: "memory");
        } else {
            asm volatile("cp.async.wait_group 0;" ::: "memory");
        }
        __syncthreads();
        compute(c);
        __syncthreads();
    }

    // ---- epilogue: bias + relu, stores into g_x ----
    float bia[2][2];
    #pragma unroll
    for (int mt = 0; mt < 2; ++mt) {
        int mb = wm * 32 + mt * 16 + (l >> 2);
        bia[mt][0] = __ldg(bias + mb);
        bia[mt][1] = __ldg(bias + mb + 8);
    }
    #pragma unroll
    for (int mt = 0; mt < 2; ++mt)
        #pragma unroll
        for (int nf = 0; nf < 8; ++nf)
            #pragma unroll
            for (int r = 0; r < 4; ++r) {
                int m = wm * 32 + mt * 16 + (l >> 2) + ((r >> 1) ? 8 : 0);
                int n = wn * 64 + nf * 8 + 2 * (l & 3) + (r & 1);
                int ng = nbase + n;
                int oh = ng / 40, ow = ng - oh * 40;
                if (oh < 39 && ow < 39) {
                    float v = acc[mt][nf][r] + bia[mt][r >> 1];
                    v = v > 0.f ? v : 0.f;
                    g_x[((size_t)(b * OC1 + m) * 39 + oh) * 39 + ow] = v;
                }
            }
}

// ---------------------------------------------------------------------------
// K2: difference conv (Wc[a+4]-Wc[a]) + global argmax over f = a*1444 + pos.
// ---------------------------------------------------------------------------
__global__ __launch_bounds__(256) void cls_argmax_kernel(
    const float* __restrict__ Wc, const float* __restrict__ bc)
{
    __shared__ __align__(16) float wds[128 * 16];
    __shared__ float xs[4 * NPOS1];
    __shared__ float rv[256];
    __shared__ int   rf[256];

    const int b = blockIdx.x, t = threadIdx.x;

    #pragma unroll
    for (int i = 0; i < 8; ++i) {
        int e = t + i * 256;
        int ic = e >> 4, tap = (e >> 2) & 3, a = e & 3;
        wds[ic * 16 + tap * 4 + a] =
            Wc[(a + 4) * 512 + ic * 4 + tap] - Wc[a * 512 + ic * 4 + tap];
    }

    int  offs[6];
    bool valid[6];
    #pragma unroll
    for (int i = 0; i < 6; ++i) {
        int p = t + i * 256;
        valid[i] = (p < KPOS);
        int pc = valid[i] ? p : 0;
        offs[i] = (pc / 38) * 39 + (pc % 38);
    }

    float acc[6][4];
    #pragma unroll
    for (int i = 0; i < 6; ++i)
        #pragma unroll
        for (int a = 0; a < 4; ++a) acc[i][a] = 0.f;

    const float* xb = g_x + (size_t)b * OC1 * NPOS1;

    for (int chunk = 0; chunk < 32; ++chunk) {
        __syncthreads();
        #pragma unroll
        for (int i = 0; i < 24; ++i) {
            int e = t + i * 256;
            if (e < 4 * NPOS1) xs[e] = xb[chunk * 4 * NPOS1 + e];
        }
        __syncthreads();
        #pragma unroll
        for (int icL = 0; icL < 4; ++icL) {
            int icg = chunk * 4 + icL;
            #pragma unroll
            for (int tap = 0; tap < 4; ++tap) {
                float4 wv = *(const float4*)&wds[icg * 16 + tap * 4];
                int bidx = icL * NPOS1 + (tap >> 1) * 39 + (tap & 1);
                #pragma unroll
                for (int i = 0; i < 6; ++i) {
                    float xv = xs[bidx + offs[i]];
                    acc[i][0] += wv.x * xv;
                    acc[i][1] += wv.y * xv;
                    acc[i][2] += wv.z * xv;
                    acc[i][3] += wv.w * xv;
                }
            }
        }
    }

    float bd[4];
    #pragma unroll
    for (int a = 0; a < 4; ++a) bd[a] = bc[a + 4] - bc[a];

    float bv = -1e30f; int bf = 0x7fffffff;
    #pragma unroll
    for (int i = 0; i < 6; ++i) {
        if (valid[i]) {
            int p = t + i * 256;
            #pragma unroll
            for (int a = 0; a < 4; ++a) {
                float v = acc[i][a] + bd[a];
                int f = a * KPOS + p;
                if (v > bv || (v == bv && f < bf)) { bv = v; bf = f; }
            }
        }
    }
    rv[t] = bv; rf[t] = bf;
    __syncthreads();
    for (int s = 128; s > 0; s >>= 1) {
        if (t < s) {
            float v2 = rv[t + s]; int f2 = rf[t + s];
            if (v2 > rv[t] || (v2 == rv[t] && f2 < rf[t])) { rv[t] = v2; rf[t] = f2; }
        }
        __syncthreads();
    }
    if (t == 0) { g_bf[b] = rf[0]; g_bv[b] = rv[0]; }
}

// ---------------------------------------------------------------------------
// K3: deltas conv only at the selected position, box assembly.
// ---------------------------------------------------------------------------
__global__ __launch_bounds__(128) void box_kernel(
    const float* __restrict__ Wb, const float* __restrict__ bb,
    const float* __restrict__ anchors, const float* __restrict__ im_info,
    float* __restrict__ out)
{
    __shared__ float red[4][128];
    const int b = blockIdx.x, ic = threadIdx.x;
    const int f  = g_bf[b];
    const int kp = f >> 2, ap = f & 3;
    const int hp = kp / 38, wp = kp % 38;

    const float* xb = g_x + ((size_t)b * OC1 + ic) * NPOS1 + hp * 39 + wp;
    float x0 = xb[0], x1 = xb[1], x2 = xb[39], x3 = xb[40];

    #pragma unroll
    for (int j = 0; j < 4; ++j) {
        const float* wq = Wb + (ap * 4 + j) * 512 + ic * 4;
        red[j][ic] = x0 * wq[0] + x1 * wq[1] + x2 * wq[2] + x3 * wq[3];
    }
    __syncthreads();
    if (ic < 4) {
        float s = 0.f;
        #pragma unroll 8
        for (int k = 0; k < 128; ++k) s += red[ic][k];
        s += bb[ap * 4 + ic];
        float shift = (ic & 1) ? hp * 16.f : wp * 16.f;
        float sc = im_info[0];
        float box = (anchors[ap * 4 + ic] + shift + s) * sc;
        out[b * 9 + ic]     = truncf(box / sc);
        out[b * 9 + 4 + ic] = box;
    }
    if (ic == 4) out[b * 9 + 8] = 1.f / (1.f + expf(-g_bv[b]));
}

// ---------------------------------------------------------------------------
// K4: proposal loss.
// ---------------------------------------------------------------------------
__global__ void loss_kernel(const float* __restrict__ gt,
                            const int* __restrict__ central,
                            float* __restrict__ out, int out_size)
{
    int idx = central[0];
    bool valid = idx < BATCH;
    int ix = idx < 0 ? 0 : (idx > BATCH - 1 ? BATCH - 1 : idx);
    float vb0 = out[ix * 9 + 4], vb1 = out[ix * 9 + 5];
    float vb2 = out[ix * 9 + 6], vb3 = out[ix * 9 + 7];
    float vs  = out[ix * 9 + 8];
    float xi1 = fmaxf(gt[0], vb0);
    float yi1 = fmaxf(gt[1], vb1);
    float xi2 = fmaxf(gt[2], vb2);
    float yi2 = fmaxf(gt[3], vb3);
    float inter = (xi2 - xi1) * (yi2 - yi1);
    float a1 = (gt[2] - gt[0]) * (gt[3] - gt[1]);
    float a2 = (vb2 - vb0) * (vb3 - vb1);
    float iou = inter / (a1 + a2 - inter);
    float lv = (iou > 0.7f) ? -logf(vs + 1e-5f) : -logf(1.f - vs + 1e-5f);
    out[out_size - 1] = valid ? lv : 0.f;
}

// ---------------------------------------------------------------------------
extern "C" void kernel_launch(void* const* d_in, const int* in_sizes, int n_in,
                              void* d_out, int out_size)
{
    const float* base_feat = (const float*)d_in[0];
    const int*   central   = (const int*)  d_in[1];
    const float* im_info   = (const float*)d_in[2];
    const float* gt_boxes  = (const float*)d_in[3];
    const float* W1        = (const float*)d_in[4];
    const float* b1        = (const float*)d_in[5];
    const float* Wc        = (const float*)d_in[6];
    const float* bc        = (const float*)d_in[7];
    const float* Wb        = (const float*)d_in[8];
    const float* bb        = (const float*)d_in[9];
    const float* anchors   = (const float*)d_in[10];
    float* out = (float*)d_out;

    cudaFuncSetAttribute(conv1_tc_kernel,
                         cudaFuncAttributeMaxDynamicSharedMemorySize, SMEM_TC);

    prep_w_kernel<<<256, 256>>>(W1);
    prep_in_kernel<<<dim3(19, 8, BATCH), 256>>>(base_feat);
    conv1_tc_kernel<<<BATCH * 13, 256, SMEM_TC>>>(b1);
    cls_argmax_kernel<<<BATCH, 256>>>(Wc, bc);
    box_kernel<<<BATCH, 128>>>(Wb, bb, anchors, im_info, out);
    loss_kernel<<<1, 1>>>(gt_boxes, central, out, out_size);
}

// round 7
// speedup vs baseline: 3.4105x; 1.5081x over previous
#include <cuda_runtime.h>
#include <cuda_fp16.h>
#include <math.h>
#include <cstdint>

#define BATCH 300
#define ICH   256
#define OC1   128
#define NPOS1 1521
#define KPOS  1444

// ------------------- device scratch -------------------
__device__ float g_x[BATCH * OC1 * NPOS1];     // conv1 output, [b][oc][oh*39+ow]
__device__ int   g_bf4[BATCH * 4];
__device__ float g_bv4[BATCH * 4];
// weight images fp16 hi/lo: [c][oc][64k], k = tap*16 + icL, 128B rows
__device__ __align__(16) unsigned char g_Ah[16 * 16384];
__device__ __align__(16) unsigned char g_Al[16 * 16384];
// position-major fp16-hi input: [b][kpos][ic]
__device__ __half g_pH[(size_t)BATCH * KPOS * ICH];

__device__ __forceinline__ uint32_t smem_u32(const void* p) {
    return (uint32_t)__cvta_generic_to_shared(p);
}
__device__ __forceinline__ void ldmx4(uint32_t* r, uint32_t addr) {
    asm volatile("ldmatrix.sync.aligned.m8n8.x4.shared.b16 {%0,%1,%2,%3}, [%4];"
        : "=r"(r[0]), "=r"(r[1]), "=r"(r[2]), "=r"(r[3]) : "r"(addr));
}
__device__ __forceinline__ void mma16816(float* d, const uint32_t* a, const uint32_t* b) {
    asm volatile("mma.sync.aligned.m16n8k16.row.col.f32.f16.f16.f32 "
        "{%0,%1,%2,%3},{%4,%5,%6,%7},{%8,%9},{%0,%1,%2,%3};"
        : "+f"(d[0]), "+f"(d[1]), "+f"(d[2]), "+f"(d[3])
        : "r"(a[0]), "r"(a[1]), "r"(a[2]), "r"(a[3]), "r"(b[0]), "r"(b[1]));
}
__device__ __forceinline__ void cpasync16z(uint32_t dst, const void* src, uint32_t sz) {
    asm volatile("cp.async.cg.shared.global [%0], [%1], 16, %2;"
        :: "r"(dst), "l"(src), "r"(sz));
}
__device__ __forceinline__ void split_h(float v, __half& h, __half& l) {
    h = __float2half(v);
    l = __float2half(v - __half2float(h));
}

// ---------------------------------------------------------------------------
// K0a: split W1 into fp16 hi/lo images [c][oc][64k], k = tap*16 + icL.
// ---------------------------------------------------------------------------
__global__ __launch_bounds__(256) void prep_w_kernel(const float* __restrict__ W1) {
    int p = blockIdx.x * 256 + threadIdx.x;   // 65536 pairs
    int oc = p >> 9;
    int kk = (p & 511) << 1;                  // even k in [0,1024)
    int c = kk >> 6, k2 = kk & 63;
    int tap = k2 >> 4, icL = k2 & 15;
    float v0 = W1[oc * 1024 + (c * 16 + icL) * 4 + tap];
    float v1 = W1[oc * 1024 + (c * 16 + icL + 1) * 4 + tap];
    __half h0, l0, h1, l1;
    split_h(v0, h0, l0);
    split_h(v1, h1, l1);
    uint32_t uh = ((uint32_t)__half_as_ushort(h1) << 16) | __half_as_ushort(h0);
    uint32_t ul = ((uint32_t)__half_as_ushort(l1) << 16) | __half_as_ushort(l0);
    uint32_t off = (uint32_t)(c * 16384 + oc * 128 + k2 * 2);
    *(uint32_t*)(g_Ah + off) = uh;
    *(uint32_t*)(g_Al + off) = ul;
}

// ---------------------------------------------------------------------------
// K0b: transpose input: [b][ic][1444] fp32 -> [b][pos][ic] fp16 (hi only).
// ---------------------------------------------------------------------------
__global__ __launch_bounds__(256) void prep_in_kernel(const float* __restrict__ in) {
    __shared__ float st[32][77];
    const int pt = blockIdx.x, icb = blockIdx.y, b = blockIdx.z;
    const int t = threadIdx.x;
    const float* src = in + ((size_t)(b * ICH + icb * 32) * KPOS) + pt * 76;
    #pragma unroll
    for (int i = 0; i < 10; ++i) {
        int e = t + i * 256;
        if (e < 2432) {
            int icL = e / 76, s = e - icL * 76;
            st[icL][s] = src[(size_t)icL * KPOS + s];
        }
    }
    __syncthreads();
    #pragma unroll
    for (int i = 0; i < 10; ++i) {
        int e = t + i * 256;
        if (e < 2432) {
            int posL = e >> 5, icL = e & 31;
            size_t d = (size_t)(b * KPOS + pt * 76 + posL) * ICH + icb * 32 + icL;
            g_pH[d] = __float2half(st[icL][posL]);
        }
    }
}

// ---------------------------------------------------------------------------
// K1: conv1, tap-decomposed fp16 2-pass split ((Ah+Al) x Bh), fp32 accum.
// CTA: 128 oc x 128 positions (40-grid), 13 tiles/batch. 8 warps 4(M)x2(N).
// ---------------------------------------------------------------------------
#define APITCH 144
#define BPITCH 48
#define OFF_AL 18432
#define OFF_B  36864
#define BUFSZ  45312
#define SMEM_TC (2 * BUFSZ)

__global__ __launch_bounds__(256, 2) void conv1_tc_kernel(
    const float* __restrict__ bias)
{
    extern __shared__ __align__(16) unsigned char sm[];
    const uint32_t smb = smem_u32(sm);
    const int t = threadIdx.x;
    const int b = blockIdx.x / 13;
    const int tile = blockIdx.x - b * 13;
    const int nbase = tile * 128;

    const int wid = t >> 5, l = t & 31;
    const int wm = wid & 3, wn = wid >> 2;
    const uint32_t aoff = (uint32_t)((wm * 32 + (l & 15)) * APITCH + ((l >> 4) & 1) * 16);
    const uint32_t boff = (uint32_t)((wn * 64 + (l & 7) + ((l >> 4) & 1) * 8) * BPITCH
                                     + ((l >> 3) & 1) * 16);

    float acc[2][8][4];
    #pragma unroll
    for (int mt = 0; mt < 2; ++mt)
        #pragma unroll
        for (int nf = 0; nf < 8; ++nf)
            #pragma unroll
            for (int r = 0; r < 4; ++r) acc[mt][nf][r] = 0.f;

    // ---- issue: async loads for chunk c into buffer c&1 ----
    auto issue = [&](int c) {
        const uint32_t bb = smb + (c & 1) * BUFSZ;
        // A: 2 planes x 128 oc x 8 segs of 16B
        #pragma unroll
        for (int i = 0; i < 8; ++i) {
            int e = t + i * 256;                 // 0..2047
            int pl = e >> 10, r = e & 1023;      // r = oc*8+seg
            const unsigned char* src = (pl ? g_Al : g_Ah) + c * 16384 + r * 16;
            cpasync16z(bb + pl * OFF_AL + (r >> 3) * APITCH + (r & 7) * 16, src, 16);
        }
        // B: 176 rows x 2 halves of 16B (row = 16 ic of one position, fp16)
        #pragma unroll
        for (int i = 0; i < 2; ++i) {
            int e = t + i * 256;
            if (e < 352) {
                int s = e >> 1, half = e & 1;
                int m = nbase - 40 + s;
                int iy = m / 40;
                int px = m - iy * 40;
                bool valid = (m >= 0) && (iy < 38) && (px >= 1) && (px <= 38);
                size_t si = valid ? ((size_t)(b * KPOS + iy * 38 + px - 1) * ICH
                                     + c * 16 + half * 8) : 0;
                cpasync16z(bb + OFF_B + s * BPITCH + half * 16,
                           g_pH + si, valid ? 16u : 0u);
            }
        }
        asm volatile("cp.async.commit_group;" ::: "memory");
    };

    // ---- compute chunk c: 4 taps, each k16, 2 split passes ----
    auto compute = [&](int c) {
        const uint32_t bb = smb + (c & 1) * BUFSZ;
        #pragma unroll
        for (int tap = 0; tap < 4; ++tap) {
            const uint32_t koff = tap * 32;
            const int dlt = (tap >> 1) * 40 + (tap & 1);
            uint32_t Ah[2][4], Al[2][4], Bh[8][2];
            ldmx4(Ah[0], bb + aoff + koff);
            ldmx4(Ah[1], bb + aoff + 16 * APITCH + koff);
            ldmx4(Al[0], bb + OFF_AL + aoff + koff);
            ldmx4(Al[1], bb + OFF_AL + aoff + 16 * APITCH + koff);
            #pragma unroll
            for (int g = 0; g < 4; ++g) {
                uint32_t r[4];
                ldmx4(r, bb + OFF_B + boff + (dlt + g * 16) * BPITCH);
                Bh[2*g][0] = r[0]; Bh[2*g][1] = r[1];
                Bh[2*g+1][0] = r[2]; Bh[2*g+1][1] = r[3];
            }
            #pragma unroll
            for (int mt = 0; mt < 2; ++mt)
                #pragma unroll
                for (int nf = 0; nf < 8; ++nf) {
                    mma16816(acc[mt][nf], Ah[mt], Bh[nf]);
                    mma16816(acc[mt][nf], Al[mt], Bh[nf]);
                }
        }
    };

    // ---- pipeline ----
    issue(0);
    for (int c = 0; c < 16; ++c) {
        if (c < 15) {
            issue(c + 1);
            asm volatile("cp.async.wait_group 1;" ::: "memory");
        } else {
            asm volatile("cp.async.wait_group 0;" ::: "memory");
        }
        __syncthreads();
        compute(c);
        __syncthreads();
    }

    // ---- epilogue: bias + relu, stores into g_x ----
    float bia[2][2];
    #pragma unroll
    for (int mt = 0; mt < 2; ++mt) {
        int mb = wm * 32 + mt * 16 + (l >> 2);
        bia[mt][0] = __ldg(bias + mb);
        bia[mt][1] = __ldg(bias + mb + 8);
    }
    #pragma unroll
    for (int mt = 0; mt < 2; ++mt)
        #pragma unroll
        for (int nf = 0; nf < 8; ++nf)
            #pragma unroll
            for (int r = 0; r < 4; ++r) {
                int m = wm * 32 + mt * 16 + (l >> 2) + ((r >> 1) ? 8 : 0);
                int n = wn * 64 + nf * 8 + 2 * (l & 3) + (r & 1);
                int ng = nbase + n;
                int oh = ng / 40, ow = ng - oh * 40;
                if (oh < 39 && ow < 39) {
                    float v = acc[mt][nf][r] + bia[mt][r >> 1];
                    v = v > 0.f ? v : 0.f;
                    g_x[((size_t)(b * OC1 + m) * 39 + oh) * 39 + ow] = v;
                }
            }
}

// ---------------------------------------------------------------------------
// K2: difference conv + partial argmax over a 361-position tile.
// grid (4 tiles, 300 batches), 256 threads. Partial (v, f) -> g_bv4/g_bf4.
// ---------------------------------------------------------------------------
__global__ __launch_bounds__(256) void cls_argmax_kernel(
    const float* __restrict__ Wc, const float* __restrict__ bc)
{
    __shared__ __align__(16) float wds[128 * 16];
    __shared__ float xs[4 * 416];
    __shared__ float rv[256];
    __shared__ int   rf[256];

    const int tb = blockIdx.x, b = blockIdx.y, t = threadIdx.x;
    const int kp0 = tb * 361;
    const int w0 = (kp0 / 38) * 39 + (kp0 % 38);
    const int kpe = kp0 + 360;
    const int wlen = (kpe / 38) * 39 + (kpe % 38) + 41 - w0;   // <= 410

    #pragma unroll
    for (int i = 0; i < 8; ++i) {
        int e = t + i * 256;
        int ic = e >> 4, tap = (e >> 2) & 3, a = e & 3;
        wds[ic * 16 + tap * 4 + a] =
            Wc[(a + 4) * 512 + ic * 4 + tap] - Wc[a * 512 + ic * 4 + tap];
    }

    int  offr[2];
    bool valid[2];
    #pragma unroll
    for (int i = 0; i < 2; ++i) {
        int pl = t + i * 256;
        valid[i] = (pl < 361);
        int p = kp0 + (valid[i] ? pl : 0);
        offr[i] = (p / 38) * 39 + (p % 38) - w0;
    }

    float acc[2][4];
    #pragma unroll
    for (int i = 0; i < 2; ++i)
        #pragma unroll
        for (int a = 0; a < 4; ++a) acc[i][a] = 0.f;

    const float* xb = g_x + (size_t)b * OC1 * NPOS1 + w0;

    for (int chunk = 0; chunk < 32; ++chunk) {
        __syncthreads();
        #pragma unroll
        for (int i = 0; i < 7; ++i) {
            int e = t + i * 256;
            if (e < 4 * 410) {
                int icL = e / 410, s = e - icL * 410;
                xs[icL * 416 + s] = (s < wlen)
                    ? xb[(size_t)(chunk * 4 + icL) * NPOS1 + s] : 0.f;
            }
        }
        __syncthreads();
        #pragma unroll
        for (int icL = 0; icL < 4; ++icL) {
            int icg = chunk * 4 + icL;
            #pragma unroll
            for (int tap = 0; tap < 4; ++tap) {
                float4 wv = *(const float4*)&wds[icg * 16 + tap * 4];
                int bidx = icL * 416 + (tap >> 1) * 39 + (tap & 1);
                #pragma unroll
                for (int i = 0; i < 2; ++i) {
                    float xv = xs[bidx + offr[i]];
                    acc[i][0] += wv.x * xv;
                    acc[i][1] += wv.y * xv;
                    acc[i][2] += wv.z * xv;
                    acc[i][3] += wv.w * xv;
                }
            }
        }
    }

    float bd[4];
    #pragma unroll
    for (int a = 0; a < 4; ++a) bd[a] = bc[a + 4] - bc[a];

    float bv = -1e30f; int bf = 0x7fffffff;
    #pragma unroll
    for (int i = 0; i < 2; ++i) {
        if (valid[i]) {
            int p = kp0 + t + i * 256;
            #pragma unroll
            for (int a = 0; a < 4; ++a) {
                float v = acc[i][a] + bd[a];
                int f = a * KPOS + p;
                if (v > bv || (v == bv && f < bf)) { bv = v; bf = f; }
            }
        }
    }
    rv[t] = bv; rf[t] = bf;
    __syncthreads();
    for (int s = 128; s > 0; s >>= 1) {
        if (t < s) {
            float v2 = rv[t + s]; int f2 = rf[t + s];
            if (v2 > rv[t] || (v2 == rv[t] && f2 < rf[t])) { rv[t] = v2; rf[t] = f2; }
        }
        __syncthreads();
    }
    if (t == 0) { g_bf4[b * 4 + tb] = rf[0]; g_bv4[b * 4 + tb] = rv[0]; }
}

// ---------------------------------------------------------------------------
// K3: merge partial argmaxes, deltas conv at selected position, box assembly.
// ---------------------------------------------------------------------------
__global__ __launch_bounds__(128) void box_kernel(
    const float* __restrict__ Wb, const float* __restrict__ bb,
    const float* __restrict__ anchors, const float* __restrict__ im_info,
    float* __restrict__ out)
{
    __shared__ float red[4][128];
    __shared__ int   sF;
    __shared__ float sV;
    const int b = blockIdx.x, ic = threadIdx.x;

    if (ic == 0) {
        float bv = -1e30f; int bf = 0x7fffffff;
        #pragma unroll
        for (int j = 0; j < 4; ++j) {
            float v = g_bv4[b * 4 + j]; int f = g_bf4[b * 4 + j];
            if (v > bv || (v == bv && f < bf)) { bv = v; bf = f; }
        }
        sF = bf; sV = bv;
    }
    __syncthreads();
    const int f  = sF;
    const int kp = f >> 2, ap = f & 3;
    const int hp = kp / 38, wp = kp % 38;

    const float* xb = g_x + ((size_t)b * OC1 + ic) * NPOS1 + hp * 39 + wp;
    float x0 = xb[0], x1 = xb[1], x2 = xb[39], x3 = xb[40];

    #pragma unroll
    for (int j = 0; j < 4; ++j) {
        const float* wq = Wb + (ap * 4 + j) * 512 + ic * 4;
        red[j][ic] = x0 * wq[0] + x1 * wq[1] + x2 * wq[2] + x3 * wq[3];
    }
    __syncthreads();
    if (ic < 4) {
        float s = 0.f;
        #pragma unroll 8
        for (int k = 0; k < 128; ++k) s += red[ic][k];
        s += bb[ap * 4 + ic];
        float shift = (ic & 1) ? hp * 16.f : wp * 16.f;
        float sc = im_info[0];
        float box = (anchors[ap * 4 + ic] + shift + s) * sc;
        out[b * 9 + ic]     = truncf(box / sc);
        out[b * 9 + 4 + ic] = box;
    }
    if (ic == 4) out[b * 9 + 8] = 1.f / (1.f + expf(-sV));
}

// ---------------------------------------------------------------------------
// K4: proposal loss.
// ---------------------------------------------------------------------------
__global__ void loss_kernel(const float* __restrict__ gt,
                            const int* __restrict__ central,
                            float* __restrict__ out, int out_size)
{
    int idx = central[0];
    bool valid = idx < BATCH;
    int ix = idx < 0 ? 0 : (idx > BATCH - 1 ? BATCH - 1 : idx);
    float vb0 = out[ix * 9 + 4], vb1 = out[ix * 9 + 5];
    float vb2 = out[ix * 9 + 6], vb3 = out[ix * 9 + 7];
    float vs  = out[ix * 9 + 8];
    float xi1 = fmaxf(gt[0], vb0);
    float yi1 = fmaxf(gt[1], vb1);
    float xi2 = fmaxf(gt[2], vb2);
    float yi2 = fmaxf(gt[3], vb3);
    float inter = (xi2 - xi1) * (yi2 - yi1);
    float a1 = (gt[2] - gt[0]) * (gt[3] - gt[1]);
    float a2 = (vb2 - vb0) * (vb3 - vb1);
    float iou = inter / (a1 + a2 - inter);
    float lv = (iou > 0.7f) ? -logf(vs + 1e-5f) : -logf(1.f - vs + 1e-5f);
    out[out_size - 1] = valid ? lv : 0.f;
}

// ---------------------------------------------------------------------------
extern "C" void kernel_launch(void* const* d_in, const int* in_sizes, int n_in,
                              void* d_out, int out_size)
{
    const float* base_feat = (const float*)d_in[0];
    const int*   central   = (const int*)  d_in[1];
    const float* im_info   = (const float*)d_in[2];
    const float* gt_boxes  = (const float*)d_in[3];
    const float* W1        = (const float*)d_in[4];
    const float* b1        = (const float*)d_in[5];
    const float* Wc        = (const float*)d_in[6];
    const float* bc        = (const float*)d_in[7];
    const float* Wb        = (const float*)d_in[8];
    const float* bb        = (const float*)d_in[9];
    const float* anchors   = (const float*)d_in[10];
    float* out = (float*)d_out;

    cudaFuncSetAttribute(conv1_tc_kernel,
                         cudaFuncAttributeMaxDynamicSharedMemorySize, SMEM_TC);

    prep_w_kernel<<<256, 256>>>(W1);
    prep_in_kernel<<<dim3(19, 8, BATCH), 256>>>(base_feat);
    conv1_tc_kernel<<<BATCH * 13, 256, SMEM_TC>>>(b1);
    cls_argmax_kernel<<<dim3(4, BATCH), 256>>>(Wc, bc);
    box_kernel<<<BATCH, 128>>>(Wb, bb, anchors, im_info, out);
    loss_kernel<<<1, 1>>>(gt_boxes, central, out, out_size);
}

// round 8
// speedup vs baseline: 3.4112x; 1.0002x over previous
#include <cuda_runtime.h>
#include <cuda_fp16.h>
#include <math.h>
#include <cstdint>

#define BATCH 300
#define ICH   256
#define OC1   128
#define NPOS1 1521
#define KPOS  1444

// ------------------- device scratch -------------------
__device__ float g_x[BATCH * OC1 * NPOS1];     // conv1 output, [b][oc][oh*39+ow]
__device__ int   g_bf4[BATCH * 4];
__device__ float g_bv4[BATCH * 4];
// weight images fp16 hi/lo: [c][oc][64k], k = tap*16 + icL, 128B rows
__device__ __align__(16) unsigned char g_Ah[16 * 16384];
__device__ __align__(16) unsigned char g_Al[16 * 16384];
// position-major fp16-hi input: [b][kpos][ic]
__device__ __half g_pH[(size_t)BATCH * KPOS * ICH];

__device__ __forceinline__ uint32_t smem_u32(const void* p) {
    return (uint32_t)__cvta_generic_to_shared(p);
}
__device__ __forceinline__ void ldmx4(uint32_t* r, uint32_t addr) {
    asm volatile("ldmatrix.sync.aligned.m8n8.x4.shared.b16 {%0,%1,%2,%3}, [%4];"
        : "=r"(r[0]), "=r"(r[1]), "=r"(r[2]), "=r"(r[3]) : "r"(addr));
}
__device__ __forceinline__ void mma16816(float* d, const uint32_t* a, const uint32_t* b) {
    asm volatile("mma.sync.aligned.m16n8k16.row.col.f32.f16.f16.f32 "
        "{%0,%1,%2,%3},{%4,%5,%6,%7},{%8,%9},{%0,%1,%2,%3};"
        : "+f"(d[0]), "+f"(d[1]), "+f"(d[2]), "+f"(d[3])
        : "r"(a[0]), "r"(a[1]), "r"(a[2]), "r"(a[3]), "r"(b[0]), "r"(b[1]));
}
__device__ __forceinline__ void cpasync16z(uint32_t dst, const void* src, uint32_t sz) {
    asm volatile("cp.async.cg.shared.global [%0], [%1], 16, %2;"
        :: "r"(dst), "l"(src), "r"(sz));
}
__device__ __forceinline__ void split_h(float v, __half& h, __half& l) {
    h = __float2half(v);
    l = __float2half(v - __half2float(h));
}

// ---------------------------------------------------------------------------
// K0a: split W1 into fp16 hi/lo images [c][oc][64k], k = tap*16 + icL.
// ---------------------------------------------------------------------------
__global__ __launch_bounds__(256) void prep_w_kernel(const float* __restrict__ W1) {
    int p = blockIdx.x * 256 + threadIdx.x;   // 65536 pairs
    int oc = p >> 9;
    int kk = (p & 511) << 1;                  // even k in [0,1024)
    int c = kk >> 6, k2 = kk & 63;
    int tap = k2 >> 4, icL = k2 & 15;
    float v0 = W1[oc * 1024 + (c * 16 + icL) * 4 + tap];
    float v1 = W1[oc * 1024 + (c * 16 + icL + 1) * 4 + tap];
    __half h0, l0, h1, l1;
    split_h(v0, h0, l0);
    split_h(v1, h1, l1);
    uint32_t uh = ((uint32_t)__half_as_ushort(h1) << 16) | __half_as_ushort(h0);
    uint32_t ul = ((uint32_t)__half_as_ushort(l1) << 16) | __half_as_ushort(l0);
    uint32_t off = (uint32_t)(c * 16384 + oc * 128 + k2 * 2);
    *(uint32_t*)(g_Ah + off) = uh;
    *(uint32_t*)(g_Al + off) = ul;
}

// ---------------------------------------------------------------------------
// K0b: transpose input: [b][ic][1444] fp32 -> [b][pos][ic] fp16 (hi only).
// ---------------------------------------------------------------------------
__global__ __launch_bounds__(256) void prep_in_kernel(const float* __restrict__ in) {
    __shared__ float st[32][77];
    const int pt = blockIdx.x, icb = blockIdx.y, b = blockIdx.z;
    const int t = threadIdx.x;
    const float* src = in + ((size_t)(b * ICH + icb * 32) * KPOS) + pt * 76;
    #pragma unroll
    for (int i = 0; i < 10; ++i) {
        int e = t + i * 256;
        if (e < 2432) {
            int icL = e / 76, s = e - icL * 76;
            st[icL][s] = src[(size_t)icL * KPOS + s];
        }
    }
    __syncthreads();
    #pragma unroll
    for (int i = 0; i < 10; ++i) {
        int e = t + i * 256;
        if (e < 2432) {
            int posL = e >> 5, icL = e & 31;
            size_t d = (size_t)(b * KPOS + pt * 76 + posL) * ICH + icb * 32 + icL;
            g_pH[d] = __float2half(st[icL][posL]);
        }
    }
}

// ---------------------------------------------------------------------------
// K1: conv1, tap-decomposed fp16 2-pass split ((Ah+Al) x Bh), fp32 accum.
// CTA: 128 oc x 128 positions (40-grid), 13 tiles/batch. 8 warps 4(M)x2(N).
// ---------------------------------------------------------------------------
#define APITCH 144
#define BPITCH 48
#define OFF_AL 18432
#define OFF_B  36864
#define BUFSZ  45312
#define SMEM_TC (2 * BUFSZ)

__global__ __launch_bounds__(256, 2) void conv1_tc_kernel(
    const float* __restrict__ bias)
{
    extern __shared__ __align__(16) unsigned char sm[];
    const uint32_t smb = smem_u32(sm);
    const int t = threadIdx.x;
    const int b = blockIdx.x / 13;
    const int tile = blockIdx.x - b * 13;
    const int nbase = tile * 128;

    const int wid = t >> 5, l = t & 31;
    const int wm = wid & 3, wn = wid >> 2;
    const uint32_t aoff = (uint32_t)((wm * 32 + (l & 15)) * APITCH + ((l >> 4) & 1) * 16);
    const uint32_t boff = (uint32_t)((wn * 64 + (l & 7) + ((l >> 4) & 1) * 8) * BPITCH
                                     + ((l >> 3) & 1) * 16);

    float acc[2][8][4];
    #pragma unroll
    for (int mt = 0; mt < 2; ++mt)
        #pragma unroll
        for (int nf = 0; nf < 8; ++nf)
            #pragma unroll
            for (int r = 0; r < 4; ++r) acc[mt][nf][r] = 0.f;

    // ---- issue: async loads for chunk c into buffer c&1 ----
    auto issue = [&](int c) {
        const uint32_t bb = smb + (c & 1) * BUFSZ;
        // A: 2 planes x 128 oc x 8 segs of 16B
        #pragma unroll
        for (int i = 0; i < 8; ++i) {
            int e = t + i * 256;                 // 0..2047
            int pl = e >> 10, r = e & 1023;      // r = oc*8+seg
            const unsigned char* src = (pl ? g_Al : g_Ah) + c * 16384 + r * 16;
            cpasync16z(bb + pl * OFF_AL + (r >> 3) * APITCH + (r & 7) * 16, src, 16);
        }
        // B: 176 rows x 2 halves of 16B (row = 16 ic of one position, fp16)
        #pragma unroll
        for (int i = 0; i < 2; ++i) {
            int e = t + i * 256;
            if (e < 352) {
                int s = e >> 1, half = e & 1;
                int m = nbase - 40 + s;
                int iy = m / 40;
                int px = m - iy * 40;
                bool valid = (m >= 0) && (iy < 38) && (px >= 1) && (px <= 38);
                size_t si = valid ? ((size_t)(b * KPOS + iy * 38 + px - 1) * ICH
                                     + c * 16 + half * 8) : 0;
                cpasync16z(bb + OFF_B + s * BPITCH + half * 16,
                           g_pH + si, valid ? 16u : 0u);
            }
        }
        asm volatile("cp.async.commit_group;" ::: "memory");
    };

    // ---- compute chunk c: 4 taps, each k16, 2 split passes ----
    auto compute = [&](int c) {
        const uint32_t bb = smb + (c & 1) * BUFSZ;
        #pragma unroll
        for (int tap = 0; tap < 4; ++tap) {
            const uint32_t koff = tap * 32;
            const int dlt = (tap >> 1) * 40 + (tap & 1);
            uint32_t Ah[2][4], Al[2][4], Bh[8][2];
            ldmx4(Ah[0], bb + aoff + koff);
            ldmx4(Ah[1], bb + aoff + 16 * APITCH + koff);
            ldmx4(Al[0], bb + OFF_AL + aoff + koff);
            ldmx4(Al[1], bb + OFF_AL + aoff + 16 * APITCH + koff);
            #pragma unroll
            for (int g = 0; g < 4; ++g) {
                uint32_t r[4];
                ldmx4(r, bb + OFF_B + boff + (dlt + g * 16) * BPITCH);
                Bh[2*g][0] = r[0]; Bh[2*g][1] = r[1];
                Bh[2*g+1][0] = r[2]; Bh[2*g+1][1] = r[3];
            }
            #pragma unroll
            for (int mt = 0; mt < 2; ++mt)
                #pragma unroll
                for (int nf = 0; nf < 8; ++nf) {
                    mma16816(acc[mt][nf], Ah[mt], Bh[nf]);
                    mma16816(acc[mt][nf], Al[mt], Bh[nf]);
                }
        }
    };

    // ---- pipeline ----
    issue(0);
    for (int c = 0; c < 16; ++c) {
        if (c < 15) {
            issue(c + 1);
            asm volatile("cp.async.wait_group 1;" ::: "memory");
        } else {
            asm volatile("cp.async.wait_group 0;" ::: "memory");
        }
        __syncthreads();
        compute(c);
        __syncthreads();
    }

    // ---- epilogue: bias + relu, stores into g_x ----
    float bia[2][2];
    #pragma unroll
    for (int mt = 0; mt < 2; ++mt) {
        int mb = wm * 32 + mt * 16 + (l >> 2);
        bia[mt][0] = __ldg(bias + mb);
        bia[mt][1] = __ldg(bias + mb + 8);
    }
    #pragma unroll
    for (int mt = 0; mt < 2; ++mt)
        #pragma unroll
        for (int nf = 0; nf < 8; ++nf)
            #pragma unroll
            for (int r = 0; r < 4; ++r) {
                int m = wm * 32 + mt * 16 + (l >> 2) + ((r >> 1) ? 8 : 0);
                int n = wn * 64 + nf * 8 + 2 * (l & 3) + (r & 1);
                int ng = nbase + n;
                int oh = ng / 40, ow = ng - oh * 40;
                if (oh < 39 && ow < 39) {
                    float v = acc[mt][nf][r] + bia[mt][r >> 1];
                    v = v > 0.f ? v : 0.f;
                    g_x[((size_t)(b * OC1 + m) * 39 + oh) * 39 + ow] = v;
                }
            }
}

// ---------------------------------------------------------------------------
// K2: difference conv + partial argmax over a 361-position tile.
// grid (4 tiles, 300 batches), 256 threads. Partial (v, f) -> g_bv4/g_bf4.
// ---------------------------------------------------------------------------
__global__ __launch_bounds__(256) void cls_argmax_kernel(
    const float* __restrict__ Wc, const float* __restrict__ bc)
{
    __shared__ __align__(16) float wds[128 * 16];
    __shared__ float xs[4 * 416];
    __shared__ float rv[256];
    __shared__ int   rf[256];

    const int tb = blockIdx.x, b = blockIdx.y, t = threadIdx.x;
    const int kp0 = tb * 361;
    const int w0 = (kp0 / 38) * 39 + (kp0 % 38);
    const int kpe = kp0 + 360;
    const int wlen = (kpe / 38) * 39 + (kpe % 38) + 41 - w0;   // <= 410

    #pragma unroll
    for (int i = 0; i < 8; ++i) {
        int e = t + i * 256;
        int ic = e >> 4, tap = (e >> 2) & 3, a = e & 3;
        wds[ic * 16 + tap * 4 + a] =
            Wc[(a + 4) * 512 + ic * 4 + tap] - Wc[a * 512 + ic * 4 + tap];
    }

    int  offr[2];
    bool valid[2];
    #pragma unroll
    for (int i = 0; i < 2; ++i) {
        int pl = t + i * 256;
        valid[i] = (pl < 361);
        int p = kp0 + (valid[i] ? pl : 0);
        offr[i] = (p / 38) * 39 + (p % 38) - w0;
    }

    float acc[2][4];
    #pragma unroll
    for (int i = 0; i < 2; ++i)
        #pragma unroll
        for (int a = 0; a < 4; ++a) acc[i][a] = 0.f;

    const float* xb = g_x + (size_t)b * OC1 * NPOS1 + w0;

    for (int chunk = 0; chunk < 32; ++chunk) {
        __syncthreads();
        #pragma unroll
        for (int i = 0; i < 7; ++i) {
            int e = t + i * 256;
            if (e < 4 * 410) {
                int icL = e / 410, s = e - icL * 410;
                xs[icL * 416 + s] = (s < wlen)
                    ? xb[(size_t)(chunk * 4 + icL) * NPOS1 + s] : 0.f;
            }
        }
        __syncthreads();
        #pragma unroll
        for (int icL = 0; icL < 4; ++icL) {
            int icg = chunk * 4 + icL;
            #pragma unroll
            for (int tap = 0; tap < 4; ++tap) {
                float4 wv = *(const float4*)&wds[icg * 16 + tap * 4];
                int bidx = icL * 416 + (tap >> 1) * 39 + (tap & 1);
                #pragma unroll
                for (int i = 0; i < 2; ++i) {
                    float xv = xs[bidx + offr[i]];
                    acc[i][0] += wv.x * xv;
                    acc[i][1] += wv.y * xv;
                    acc[i][2] += wv.z * xv;
                    acc[i][3] += wv.w * xv;
                }
            }
        }
    }

    float bd[4];
    #pragma unroll
    for (int a = 0; a < 4; ++a) bd[a] = bc[a + 4] - bc[a];

    float bv = -1e30f; int bf = 0x7fffffff;
    #pragma unroll
    for (int i = 0; i < 2; ++i) {
        if (valid[i]) {
            int p = kp0 + t + i * 256;
            #pragma unroll
            for (int a = 0; a < 4; ++a) {
                float v = acc[i][a] + bd[a];
                int f = a * KPOS + p;
                if (v > bv || (v == bv && f < bf)) { bv = v; bf = f; }
            }
        }
    }
    rv[t] = bv; rf[t] = bf;
    __syncthreads();
    for (int s = 128; s > 0; s >>= 1) {
        if (t < s) {
            float v2 = rv[t + s]; int f2 = rf[t + s];
            if (v2 > rv[t] || (v2 == rv[t] && f2 < rf[t])) { rv[t] = v2; rf[t] = f2; }
        }
        __syncthreads();
    }
    if (t == 0) { g_bf4[b * 4 + tb] = rf[0]; g_bv4[b * 4 + tb] = rv[0]; }
}

// ---------------------------------------------------------------------------
// K3: merge partial argmaxes, deltas conv at selected position, box assembly.
// ---------------------------------------------------------------------------
__global__ __launch_bounds__(128) void box_kernel(
    const float* __restrict__ Wb, const float* __restrict__ bb,
    const float* __restrict__ anchors, const float* __restrict__ im_info,
    float* __restrict__ out)
{
    __shared__ float red[4][128];
    __shared__ int   sF;
    __shared__ float sV;
    const int b = blockIdx.x, ic = threadIdx.x;

    if (ic == 0) {
        float bv = -1e30f; int bf = 0x7fffffff;
        #pragma unroll
        for (int j = 0; j < 4; ++j) {
            float v = g_bv4[b * 4 + j]; int f = g_bf4[b * 4 + j];
            if (v > bv || (v == bv && f < bf)) { bv = v; bf = f; }
        }
        sF = bf; sV = bv;
    }
    __syncthreads();
    const int f  = sF;
    const int kp = f >> 2, ap = f & 3;
    const int hp = kp / 38, wp = kp % 38;

    const float* xb = g_x + ((size_t)b * OC1 + ic) * NPOS1 + hp * 39 + wp;
    float x0 = xb[0], x1 = xb[1], x2 = xb[39], x3 = xb[40];

    #pragma unroll
    for (int j = 0; j < 4; ++j) {
        const float* wq = Wb + (ap * 4 + j) * 512 + ic * 4;
        red[j][ic] = x0 * wq[0] + x1 * wq[1] + x2 * wq[2] + x3 * wq[3];
    }
    __syncthreads();
    if (ic < 4) {
        float s = 0.f;
        #pragma unroll 8
        for (int k = 0; k < 128; ++k) s += red[ic][k];
        s += bb[ap * 4 + ic];
        float shift = (ic & 1) ? hp * 16.f : wp * 16.f;
        float sc = im_info[0];
        float box = (anchors[ap * 4 + ic] + shift + s) * sc;
        out[b * 9 + ic]     = truncf(box / sc);
        out[b * 9 + 4 + ic] = box;
    }
    if (ic == 4) out[b * 9 + 8] = 1.f / (1.f + expf(-sV));
}

// ---------------------------------------------------------------------------
// K4: proposal loss.
// ---------------------------------------------------------------------------
__global__ void loss_kernel(const float* __restrict__ gt,
                            const int* __restrict__ central,
                            float* __restrict__ out, int out_size)
{
    int idx = central[0];
    bool valid = idx < BATCH;
    int ix = idx < 0 ? 0 : (idx > BATCH - 1 ? BATCH - 1 : idx);
    float vb0 = out[ix * 9 + 4], vb1 = out[ix * 9 + 5];
    float vb2 = out[ix * 9 + 6], vb3 = out[ix * 9 + 7];
    float vs  = out[ix * 9 + 8];
    float xi1 = fmaxf(gt[0], vb0);
    float yi1 = fmaxf(gt[1], vb1);
    float xi2 = fmaxf(gt[2], vb2);
    float yi2 = fmaxf(gt[3], vb3);
    float inter = (xi2 - xi1) * (yi2 - yi1);
    float a1 = (gt[2] - gt[0]) * (gt[3] - gt[1]);
    float a2 = (vb2 - vb0) * (vb3 - vb1);
    float iou = inter / (a1 + a2 - inter);
    float lv = (iou > 0.7f) ? -logf(vs + 1e-5f) : -logf(1.f - vs + 1e-5f);
    out[out_size - 1] = valid ? lv : 0.f;
}

// ---------------------------------------------------------------------------
extern "C" void kernel_launch(void* const* d_in, const int* in_sizes, int n_in,
                              void* d_out, int out_size)
{
    const float* base_feat = (const float*)d_in[0];
    const int*   central   = (const int*)  d_in[1];
    const float* im_info   = (const float*)d_in[2];
    const float* gt_boxes  = (const float*)d_in[3];
    const float* W1        = (const float*)d_in[4];
    const float* b1        = (const float*)d_in[5];
    const float* Wc        = (const float*)d_in[6];
    const float* bc        = (const float*)d_in[7];
    const float* Wb        = (const float*)d_in[8];
    const float* bb        = (const float*)d_in[9];
    const float* anchors   = (const float*)d_in[10];
    float* out = (float*)d_out;

    cudaFuncSetAttribute(conv1_tc_kernel,
                         cudaFuncAttributeMaxDynamicSharedMemorySize, SMEM_TC);

    prep_w_kernel<<<256, 256>>>(W1);
    prep_in_kernel<<<dim3(19, 8, BATCH), 256>>>(base_feat);
    conv1_tc_kernel<<<BATCH * 13, 256, SMEM_TC>>>(b1);
    cls_argmax_kernel<<<dim3(4, BATCH), 256>>>(Wc, bc);
    box_kernel<<<BATCH, 128>>>(Wb, bb, anchors, im_info, out);
    loss_kernel<<<1, 1>>>(gt_boxes, central, out, out_size);
}

// round 10
// speedup vs baseline: 3.9549x; 1.1594x over previous
#include <cuda_runtime.h>
#include <cuda_fp16.h>
#include <math.h>
#include <cstdint>

#define BATCH 300
#define ICH   256
#define OC1   128
#define NPOS1 1521
#define KPOS  1444

// ------------------- device scratch -------------------
__device__ float g_x[BATCH * OC1 * NPOS1];     // conv1 output (approx), [b][oc][oh*39+ow]
__device__ int   g_cp[BATCH * 6];              // candidate positions (top-2 per 3 tiles)
// weight image fp16 hi: [c][oc][64k], k = tap*16 + icL, 128B rows
__device__ __align__(16) unsigned char g_Ah[16 * 16384];
// position-major fp16-hi input: [b][kpos][ic]
__device__ __half g_pH[(size_t)BATCH * KPOS * ICH];

__device__ __forceinline__ uint32_t smem_u32(const void* p) {
    return (uint32_t)__cvta_generic_to_shared(p);
}
__device__ __forceinline__ void ldmx4(uint32_t* r, uint32_t addr) {
    asm volatile("ldmatrix.sync.aligned.m8n8.x4.shared.b16 {%0,%1,%2,%3}, [%4];"
        : "=r"(r[0]), "=r"(r[1]), "=r"(r[2]), "=r"(r[3]) : "r"(addr));
}
__device__ __forceinline__ void mma16816(float* d, const uint32_t* a, const uint32_t* b) {
    asm volatile("mma.sync.aligned.m16n8k16.row.col.f32.f16.f16.f32 "
        "{%0,%1,%2,%3},{%4,%5,%6,%7},{%8,%9},{%0,%1,%2,%3};"
        : "+f"(d[0]), "+f"(d[1]), "+f"(d[2]), "+f"(d[3])
        : "r"(a[0]), "r"(a[1]), "r"(a[2]), "r"(a[3]), "r"(b[0]), "r"(b[1]));
}
__device__ __forceinline__ void cpasync16z(uint32_t dst, const void* src, uint32_t sz) {
    asm volatile("cp.async.cg.shared.global [%0], [%1], 16, %2;"
        :: "r"(dst), "l"(src), "r"(sz));
}
__device__ __forceinline__ bool better(float v, int p, float w, int q) {
    return v > w || (v == w && p < q);
}

// ---------------------------------------------------------------------------
// K0a: W1 -> fp16 hi image [c][oc][64k], k = tap*16 + icL.
// ---------------------------------------------------------------------------
__global__ __launch_bounds__(256) void prep_w_kernel(const float* __restrict__ W1) {
    int p = blockIdx.x * 256 + threadIdx.x;   // 65536 pairs
    int oc = p >> 9;
    int kk = (p & 511) << 1;                  // even k in [0,1024)
    int c = kk >> 6, k2 = kk & 63;
    int tap = k2 >> 4, icL = k2 & 15;
    __half h0 = __float2half(W1[oc * 1024 + (c * 16 + icL) * 4 + tap]);
    __half h1 = __float2half(W1[oc * 1024 + (c * 16 + icL + 1) * 4 + tap]);
    uint32_t uh = ((uint32_t)__half_as_ushort(h1) << 16) | __half_as_ushort(h0);
    *(uint32_t*)(g_Ah + (uint32_t)(c * 16384 + oc * 128 + k2 * 2)) = uh;
}

// ---------------------------------------------------------------------------
// K0b: transpose input: [b][ic][1444] fp32 -> [b][pos][ic] fp16.
// ---------------------------------------------------------------------------
__global__ __launch_bounds__(256) void prep_in_kernel(const float* __restrict__ in) {
    __shared__ float st[32][77];
    const int pt = blockIdx.x, icb = blockIdx.y, b = blockIdx.z;
    const int t = threadIdx.x;
    const float* src = in + ((size_t)(b * ICH + icb * 32) * KPOS) + pt * 76;
    #pragma unroll
    for (int i = 0; i < 10; ++i) {
        int e = t + i * 256;
        if (e < 2432) {
            int icL = e / 76, s = e - icL * 76;
            st[icL][s] = src[(size_t)icL * KPOS + s];
        }
    }
    __syncthreads();
    #pragma unroll
    for (int i = 0; i < 10; ++i) {
        int e = t + i * 256;
        if (e < 2432) {
            int posL = e >> 5, icL = e & 31;
            size_t d = (size_t)(b * KPOS + pt * 76 + posL) * ICH + icb * 32 + icL;
            g_pH[d] = __float2half(st[icL][posL]);
        }
    }
}

// ---------------------------------------------------------------------------
// K1: conv1, tap-decomposed 1-pass fp16 (Ah x Bh), fp32 accum.
// CTA: 128 oc x 128 positions (40-grid), 13 tiles/batch. 8 warps 4(M)x2(N).
// 3-stage cp.async pipeline, one __syncthreads per chunk.
// ---------------------------------------------------------------------------
#define APITCH 144
#define BPITCH 48
#define OFF_B  18432
#define BUFSZ  35328
#define SMEM_TC (3 * BUFSZ)

__global__ __launch_bounds__(256, 2) void conv1_tc_kernel(
    const float* __restrict__ bias)
{
    extern __shared__ __align__(16) unsigned char sm[];
    const uint32_t smb = smem_u32(sm);
    const int t = threadIdx.x;
    const int b = blockIdx.x / 13;
    const int tile = blockIdx.x - b * 13;
    const int nbase = tile * 128;

    const int wid = t >> 5, l = t & 31;
    const int wm = wid & 3, wn = wid >> 2;
    const uint32_t aoff = (uint32_t)((wm * 32 + (l & 15)) * APITCH + ((l >> 4) & 1) * 16);
    const uint32_t boff = (uint32_t)((wn * 64 + (l & 7) + ((l >> 4) & 1) * 8) * BPITCH
                                     + ((l >> 3) & 1) * 16);

    float acc[2][8][4];
    #pragma unroll
    for (int mt = 0; mt < 2; ++mt)
        #pragma unroll
        for (int nf = 0; nf < 8; ++nf)
            #pragma unroll
            for (int r = 0; r < 4; ++r) acc[mt][nf][r] = 0.f;

    auto issue = [&](int c) {
        const uint32_t bb = smb + (c % 3) * BUFSZ;
        #pragma unroll
        for (int i = 0; i < 4; ++i) {
            int r = t + i * 256;                 // 0..1023 = oc*8+seg
            cpasync16z(bb + (r >> 3) * APITCH + (r & 7) * 16,
                       g_Ah + c * 16384 + r * 16, 16);
        }
        #pragma unroll
        for (int i = 0; i < 2; ++i) {
            int e = t + i * 256;
            if (e < 352) {
                int s = e >> 1, half = e & 1;
                int m = nbase - 40 + s;
                int iy = m / 40;
                int px = m - iy * 40;
                bool valid = (m >= 0) && (iy < 38) && (px >= 1) && (px <= 38);
                size_t si = valid ? ((size_t)(b * KPOS + iy * 38 + px - 1) * ICH
                                     + c * 16 + half * 8) : 0;
                cpasync16z(bb + OFF_B + s * BPITCH + half * 16,
                           g_pH + si, valid ? 16u : 0u);
            }
        }
        asm volatile("cp.async.commit_group;" ::: "memory");
    };

    auto compute = [&](int c) {
        const uint32_t bb = smb + (c % 3) * BUFSZ;
        #pragma unroll
        for (int tap = 0; tap < 4; ++tap) {
            const uint32_t koff = tap * 32;
            const int dlt = (tap >> 1) * 40 + (tap & 1);
            uint32_t Ah[2][4], Bh[8][2];
            ldmx4(Ah[0], bb + aoff + koff);
            ldmx4(Ah[1], bb + aoff + 16 * APITCH + koff);
            #pragma unroll
            for (int g = 0; g < 4; ++g) {
                uint32_t r[4];
                ldmx4(r, bb + OFF_B + boff + (dlt + g * 16) * BPITCH);
                Bh[2*g][0] = r[0]; Bh[2*g][1] = r[1];
                Bh[2*g+1][0] = r[2]; Bh[2*g+1][1] = r[3];
            }
            #pragma unroll
            for (int mt = 0; mt < 2; ++mt)
                #pragma unroll
                for (int nf = 0; nf < 8; ++nf)
                    mma16816(acc[mt][nf], Ah[mt], Bh[nf]);
        }
    };

    issue(0);
    issue(1);
    for (int c = 0; c < 16; ++c) {
        if (c == 15) {
            asm volatile("cp.async.wait_group 0;" ::: "memory");
        } else {
            asm volatile("cp.async.wait_group 1;" ::: "memory");
        }
        __syncthreads();
        if (c < 14) issue(c + 2);
        compute(c);
    }

    float bia[2][2];
    #pragma unroll
    for (int mt = 0; mt < 2; ++mt) {
        int mb = wm * 32 + mt * 16 + (l >> 2);
        bia[mt][0] = __ldg(bias + mb);
        bia[mt][1] = __ldg(bias + mb + 8);
    }
    #pragma unroll
    for (int mt = 0; mt < 2; ++mt)
        #pragma unroll
        for (int nf = 0; nf < 8; ++nf)
            #pragma unroll
            for (int r = 0; r < 4; ++r) {
                int m = wm * 32 + mt * 16 + (l >> 2) + ((r >> 1) ? 8 : 0);
                int n = wn * 64 + nf * 8 + 2 * (l & 3) + (r & 1);
                int ng = nbase + n;
                int oh = ng / 40, ow = ng - oh * 40;
                if (oh < 39 && ow < 39) {
                    float v = acc[mt][nf][r] + bia[mt][r >> 1];
                    v = v > 0.f ? v : 0.f;
                    g_x[((size_t)(b * OC1 + m) * 39 + oh) * 39 + ow] = v;
                }
            }
}

// ---------------------------------------------------------------------------
// K2: approx difference conv over a 512-position tile; emit TOP-2 positions
// per tile (by per-position channel-max). grid (3 tiles, 300 batches).
// ---------------------------------------------------------------------------
#define XSW 576

__global__ __launch_bounds__(256) void cls_argmax_kernel(
    const float* __restrict__ Wc, const float* __restrict__ bc)
{
    __shared__ __align__(16) float wds[128 * 16];
    __shared__ float xs[4 * XSW];
    __shared__ float rv1[256], rv2[256];
    __shared__ int   rp1[256], rp2[256];

    const int tb = blockIdx.x, b = blockIdx.y, t = threadIdx.x;
    const int kp0 = tb * 512;
    const int w0 = (kp0 / 38) * 39 + (kp0 % 38);
    const int kpe = (kp0 + 511 < KPOS) ? kp0 + 511 : KPOS - 1;
    const int wlen = (kpe / 38) * 39 + (kpe % 38) + 41 - w0;   // <= 565

    #pragma unroll
    for (int i = 0; i < 8; ++i) {
        int e = t + i * 256;
        int ic = e >> 4, tap = (e >> 2) & 3, a = e & 3;
        wds[ic * 16 + tap * 4 + a] =
            Wc[(a + 4) * 512 + ic * 4 + tap] - Wc[a * 512 + ic * 4 + tap];
    }

    int  offr[2];
    bool valid[2];
    #pragma unroll
    for (int i = 0; i < 2; ++i) {
        int pl = t + i * 256;
        valid[i] = (kp0 + pl < KPOS) && (pl < 512);
        int p = kp0 + (valid[i] ? pl : 0);
        offr[i] = (p / 38) * 39 + (p % 38) - w0;
    }

    float acc[2][4];
    #pragma unroll
    for (int i = 0; i < 2; ++i)
        #pragma unroll
        for (int a = 0; a < 4; ++a) acc[i][a] = 0.f;

    const float* xb = g_x + (size_t)b * OC1 * NPOS1 + w0;

    for (int chunk = 0; chunk < 32; ++chunk) {
        __syncthreads();
        #pragma unroll
        for (int i = 0; i < 9; ++i) {
            int e = t + i * 256;
            if (e < 4 * XSW) {
                int icL = e / XSW, s = e - icL * XSW;
                xs[e] = (s < wlen)
                    ? xb[(size_t)(chunk * 4 + icL) * NPOS1 + s] : 0.f;
            }
        }
        __syncthreads();
        #pragma unroll
        for (int icL = 0; icL < 4; ++icL) {
            int icg = chunk * 4 + icL;
            #pragma unroll
            for (int tap = 0; tap < 4; ++tap) {
                float4 wv = *(const float4*)&wds[icg * 16 + tap * 4];
                int bidx = icL * XSW + (tap >> 1) * 39 + (tap & 1);
                #pragma unroll
                for (int i = 0; i < 2; ++i) {
                    float xv = xs[bidx + offr[i]];
                    acc[i][0] += wv.x * xv;
                    acc[i][1] += wv.y * xv;
                    acc[i][2] += wv.z * xv;
                    acc[i][3] += wv.w * xv;
                }
            }
        }
    }

    float bd[4];
    #pragma unroll
    for (int a = 0; a < 4; ++a) bd[a] = bc[a + 4] - bc[a];

    // per-thread top-2 positions by channel-max
    float v1 = -1e30f, v2 = -1e30f;
    int p1 = 0x7fffffff, p2 = 0x7fffffff;
    #pragma unroll
    for (int i = 0; i < 2; ++i) {
        if (valid[i]) {
            int pp = kp0 + t + i * 256;
            float pv = acc[i][0] + bd[0];
            #pragma unroll
            for (int a = 1; a < 4; ++a) {
                float v = acc[i][a] + bd[a];
                if (v > pv) pv = v;
            }
            if (better(pv, pp, v1, p1)) { v2 = v1; p2 = p1; v1 = pv; p1 = pp; }
            else if (better(pv, pp, v2, p2)) { v2 = pv; p2 = pp; }
        }
    }
    rv1[t] = v1; rp1[t] = p1; rv2[t] = v2; rp2[t] = p2;
    __syncthreads();
    for (int s = 128; s > 0; s >>= 1) {
        if (t < s) {
            float a1 = rv1[t], a2 = rv2[t];
            int   e1 = rp1[t], e2 = rp2[t];
            float w1 = rv1[t + s], w2 = rv2[t + s];
            int   q1 = rp1[t + s], q2 = rp2[t + s];
            float n1, n2; int m1, m2;
            if (better(a1, e1, w1, q1)) {
                n1 = a1; m1 = e1;
                if (better(w1, q1, a2, e2)) { n2 = w1; m2 = q1; }
                else                        { n2 = a2; m2 = e2; }
            } else {
                n1 = w1; m1 = q1;
                if (better(a1, e1, w2, q2)) { n2 = a1; m2 = e1; }
                else                        { n2 = w2; m2 = q2; }
            }
            rv1[t] = n1; rp1[t] = m1; rv2[t] = n2; rp2[t] = m2;
        }
        __syncthreads();
    }
    if (t == 0) {
        g_cp[b * 6 + tb * 2]     = rp1[0];
        g_cp[b * 6 + tb * 2 + 1] = rp2[0];
    }
}

// ---------------------------------------------------------------------------
// K3: exact re-scoring of the 6 candidates + exact box.
// 256 threads: half = t>>7 (ic half), oc = t&127.
// dyn smem: sfeat [6][256][9] | sxa [6][128][4] | red6 [6][4][128]
// ---------------------------------------------------------------------------
#define SF_SZ   13824
#define SXA_OFF 13824
#define RED_OFF 16896
#define K3_SMEM ((SF_SZ + 3072 + 3072) * 4)

__global__ __launch_bounds__(256) void box_kernel(
    const float* __restrict__ in, const float* __restrict__ W1,
    const float* __restrict__ b1,
    const float* __restrict__ Wc, const float* __restrict__ bc,
    const float* __restrict__ Wb, const float* __restrict__ bb,
    const float* __restrict__ anchors, const float* __restrict__ im_info,
    float* __restrict__ out)
{
    extern __shared__ float dsm[];
    float* sfeat = dsm;
    float* sxa   = dsm + SXA_OFF;
    float* red6  = dsm + RED_OFF;
    __shared__ float sc[24];
    __shared__ int   sWin;
    __shared__ float sWinV;

    const int b = blockIdx.x, t = threadIdx.x;
    const int half = t >> 7, oc = t & 127;

    // ---- stage 6 candidate patches ----
    #pragma unroll
    for (int i = 0; i < 54; ++i) {
        int e = t + i * 256;            // cand*2304 + ic*9 + p
        int cand = e / 2304, r = e - cand * 2304;
        int ic = r / 9, p = r - ic * 9;
        int pos = g_cp[b * 6 + cand];
        int rr = pos / 38 - 1 + p / 3, cc = pos % 38 - 1 + p % 3;
        sfeat[e] = (rr >= 0 && rr < 38 && cc >= 0 && cc < 38)
                 ? in[((size_t)(b * ICH + ic) * 38 + rr) * 38 + cc] : 0.f;
    }
    __syncthreads();

    // ---- exact conv1 partials at 4 tap positions for each candidate ----
    float xa[6][4];
    #pragma unroll
    for (int c = 0; c < 6; ++c)
        #pragma unroll
        for (int j = 0; j < 4; ++j) xa[c][j] = 0.f;
    const float4* wrow = (const float4*)(W1 + oc * 1024) + half * 128;
    for (int icl = 0; icl < 128; ++icl) {
        float4 w = wrow[icl];
        int ic = half * 128 + icl;
        #pragma unroll
        for (int c = 0; c < 6; ++c) {
            const float* sf = &sfeat[c * 2304 + ic * 9];
            float s0 = sf[0], s1 = sf[1], s2 = sf[2];
            float s3 = sf[3], s4 = sf[4], s5 = sf[5];
            float s6 = sf[6], s7 = sf[7], s8 = sf[8];
            xa[c][0] += w.x * s0 + w.y * s1 + w.z * s3 + w.w * s4;
            xa[c][1] += w.x * s1 + w.y * s2 + w.z * s4 + w.w * s5;
            xa[c][2] += w.x * s3 + w.y * s4 + w.z * s6 + w.w * s7;
            xa[c][3] += w.x * s4 + w.y * s5 + w.z * s7 + w.w * s8;
        }
    }
    if (half == 0)
        #pragma unroll
        for (int c = 0; c < 6; ++c)
            #pragma unroll
            for (int j = 0; j < 4; ++j) sxa[c * 512 + oc * 4 + j] = xa[c][j];
    __syncthreads();
    if (half == 1)
        #pragma unroll
        for (int c = 0; c < 6; ++c)
            #pragma unroll
            for (int j = 0; j < 4; ++j) sxa[c * 512 + oc * 4 + j] += xa[c][j];
    __syncthreads();

    // ---- exact candidate scores ----
    if (half == 0) {
        float wd[4][4];
        #pragma unroll
        for (int ch = 0; ch < 4; ++ch)
            #pragma unroll
            for (int tp = 0; tp < 4; ++tp)
                wd[ch][tp] = Wc[(ch + 4) * 512 + oc * 4 + tp]
                           - Wc[ch * 512 + oc * 4 + tp];
        float bv1 = b1[oc];
        #pragma unroll
        for (int c = 0; c < 6; ++c) {
            float x0 = fmaxf(sxa[c * 512 + oc * 4 + 0] + bv1, 0.f);
            float x1 = fmaxf(sxa[c * 512 + oc * 4 + 1] + bv1, 0.f);
            float x2 = fmaxf(sxa[c * 512 + oc * 4 + 2] + bv1, 0.f);
            float x3 = fmaxf(sxa[c * 512 + oc * 4 + 3] + bv1, 0.f);
            #pragma unroll
            for (int ch = 0; ch < 4; ++ch)
                red6[c * 512 + ch * 128 + oc] =
                    wd[ch][0] * x0 + wd[ch][1] * x1 + wd[ch][2] * x2 + wd[ch][3] * x3;
        }
    }
    __syncthreads();
    if (t < 24) {
        int c = t >> 2, ch = t & 3;
        float s = 0.f;
        #pragma unroll 8
        for (int k = 0; k < 128; ++k) s += red6[c * 512 + ch * 128 + k];
        sc[t] = s + bc[ch + 4] - bc[ch];
    }
    __syncthreads();
    if (t == 0) {
        float bv = -1e30f; int bf = 0x7fffffff;
        for (int c = 0; c < 6; ++c) {
            int pos = g_cp[b * 6 + c];
            for (int ch = 0; ch < 4; ++ch) {
                float v = sc[c * 4 + ch];
                int f = ch * KPOS + pos;
                if (v > bv || (v == bv && f < bf)) { bv = v; bf = f; }
            }
        }
        sWin = bf; sWinV = bv;
    }
    __syncthreads();

    // ---- exact x at the decoded PROPOSAL position kp = f>>2 ----
    const int f = sWin;
    const int kp = f >> 2, ap = f & 3;
    const int hp = kp / 38, wp = kp % 38;
    #pragma unroll
    for (int i = 0; i < 9; ++i) {
        int e = t + i * 256;
        if (e < 2304) {
            int ic = e / 9, p = e - ic * 9;
            int rr = hp - 1 + p / 3, cc = wp - 1 + p % 3;
            sfeat[e] = (rr >= 0 && rr < 38 && cc >= 0 && cc < 38)
                     ? in[((size_t)(b * ICH + ic) * 38 + rr) * 38 + cc] : 0.f;
        }
    }
    __syncthreads();
    float xw[4] = {0.f, 0.f, 0.f, 0.f};
    for (int icl = 0; icl < 128; ++icl) {
        float4 w = wrow[icl];
        int ic = half * 128 + icl;
        const float* sf = &sfeat[ic * 9];
        float s0 = sf[0], s1 = sf[1], s2 = sf[2];
        float s3 = sf[3], s4 = sf[4], s5 = sf[5];
        float s6 = sf[6], s7 = sf[7], s8 = sf[8];
        xw[0] += w.x * s0 + w.y * s1 + w.z * s3 + w.w * s4;
        xw[1] += w.x * s1 + w.y * s2 + w.z * s4 + w.w * s5;
        xw[2] += w.x * s3 + w.y * s4 + w.z * s6 + w.w * s7;
        xw[3] += w.x * s4 + w.y * s5 + w.z * s7 + w.w * s8;
    }
    if (half == 0)
        #pragma unroll
        for (int j = 0; j < 4; ++j) sxa[oc * 4 + j] = xw[j];
    __syncthreads();
    if (half == 1)
        #pragma unroll
        for (int j = 0; j < 4; ++j) sxa[oc * 4 + j] += xw[j];
    __syncthreads();

    // ---- exact deltas conv + box ----
    if (half == 0) {
        float bv1 = b1[oc];
        float x0 = fmaxf(sxa[oc * 4 + 0] + bv1, 0.f);
        float x1 = fmaxf(sxa[oc * 4 + 1] + bv1, 0.f);
        float x2 = fmaxf(sxa[oc * 4 + 2] + bv1, 0.f);
        float x3 = fmaxf(sxa[oc * 4 + 3] + bv1, 0.f);
        #pragma unroll
        for (int j = 0; j < 4; ++j) {
            const float* wq = Wb + (ap * 4 + j) * 512 + oc * 4;
            red6[j * 128 + oc] = x0 * wq[0] + x1 * wq[1] + x2 * wq[2] + x3 * wq[3];
        }
    }
    __syncthreads();
    if (t < 4) {
        float s = 0.f;
        #pragma unroll 8
        for (int k = 0; k < 128; ++k) s += red6[t * 128 + k];
        s += bb[ap * 4 + t];
        float shift = (t & 1) ? hp * 16.f : wp * 16.f;
        float scv = im_info[0];
        float box = (anchors[ap * 4 + t] + shift + s) * scv;
        out[b * 9 + t]     = truncf(box / scv);
        out[b * 9 + 4 + t] = box;
    }
    if (t == 4) out[b * 9 + 8] = 1.f / (1.f + expf(-sWinV));
}

// ---------------------------------------------------------------------------
// K4: proposal loss.
// ---------------------------------------------------------------------------
__global__ void loss_kernel(const float* __restrict__ gt,
                            const int* __restrict__ central,
                            float* __restrict__ out, int out_size)
{
    int idx = central[0];
    bool valid = idx < BATCH;
    int ix = idx < 0 ? 0 : (idx > BATCH - 1 ? BATCH - 1 : idx);
    float vb0 = out[ix * 9 + 4], vb1 = out[ix * 9 + 5];
    float vb2 = out[ix * 9 + 6], vb3 = out[ix * 9 + 7];
    float vs  = out[ix * 9 + 8];
    float xi1 = fmaxf(gt[0], vb0);
    float yi1 = fmaxf(gt[1], vb1);
    float xi2 = fmaxf(gt[2], vb2);
    float yi2 = fmaxf(gt[3], vb3);
    float inter = (xi2 - xi1) * (yi2 - yi1);
    float a1 = (gt[2] - gt[0]) * (gt[3] - gt[1]);
    float a2 = (vb2 - vb0) * (vb3 - vb1);
    float iou = inter / (a1 + a2 - inter);
    float lv = (iou > 0.7f) ? -logf(vs + 1e-5f) : -logf(1.f - vs + 1e-5f);
    out[out_size - 1] = valid ? lv : 0.f;
}

// ---------------------------------------------------------------------------
extern "C" void kernel_launch(void* const* d_in, const int* in_sizes, int n_in,
                              void* d_out, int out_size)
{
    const float* base_feat = (const float*)d_in[0];
    const int*   central   = (const int*)  d_in[1];
    const float* im_info   = (const float*)d_in[2];
    const float* gt_boxes  = (const float*)d_in[3];
    const float* W1        = (const float*)d_in[4];
    const float* b1        = (const float*)d_in[5];
    const float* Wc        = (const float*)d_in[6];
    const float* bc        = (const float*)d_in[7];
    const float* Wb        = (const float*)d_in[8];
    const float* bb        = (const float*)d_in[9];
    const float* anchors   = (const float*)d_in[10];
    float* out = (float*)d_out;

    cudaFuncSetAttribute(conv1_tc_kernel,
                         cudaFuncAttributeMaxDynamicSharedMemorySize, SMEM_TC);
    cudaFuncSetAttribute(box_kernel,
                         cudaFuncAttributeMaxDynamicSharedMemorySize, K3_SMEM);

    prep_w_kernel<<<256, 256>>>(W1);
    prep_in_kernel<<<dim3(19, 8, BATCH), 256>>>(base_feat);
    conv1_tc_kernel<<<BATCH * 13, 256, SMEM_TC>>>(b1);
    cls_argmax_kernel<<<dim3(3, BATCH), 256>>>(Wc, bc);
    box_kernel<<<BATCH, 256, K3_SMEM>>>(base_feat, W1, b1, Wc, bc,
                                        Wb, bb, anchors, im_info, out);
    loss_kernel<<<1, 1>>>(gt_boxes, central, out, out_size);
}